// round 1
// baseline (speedup 1.0000x reference)
#include <cuda_runtime.h>

#define Bc 4
#define Tc 2048
#define Cc 1024
#define Dc 64
#define BT (Bc*Tc)

// Scratch for Q, K, V projections (allocation-free rule => __device__ globals)
__device__ float g_Q[BT*Dc];
__device__ float g_K[BT*Dc];
__device__ float g_V[BT*Dc];

// ---------------------------------------------------------------------------
// Kernel 1: QKV projection.  grid = (BT/64, 3), block = 256
// Computes O = x @ W + b for one of {Q,K,V} per blockIdx.y.
// Tile: 64 rows x 64 cols, K-chunks of 16. Thread (tx,ty) owns 4x4 outputs.
// ---------------------------------------------------------------------------
__global__ __launch_bounds__(256) void qkv_kernel(
    const float* __restrict__ x,
    const float* __restrict__ Wq, const float* __restrict__ bq,
    const float* __restrict__ Wk, const float* __restrict__ bk,
    const float* __restrict__ Wv, const float* __restrict__ bv)
{
    __shared__ float xsT[16*68];   // transposed x tile [k][row], pad 68 (f4-aligned)
    __shared__ float ws [16*64];   // W tile [k][col]

    const int tid = threadIdx.x;
    const int which = blockIdx.y;
    const float* W;  const float* bias;  float* O;
    if (which == 0)      { W = Wq; bias = bq; O = g_Q; }
    else if (which == 1) { W = Wk; bias = bk; O = g_K; }
    else                 { W = Wv; bias = bv; O = g_V; }

    const int m0 = blockIdx.x * 64;
    const int tx = tid & 15;       // output col group
    const int ty = tid >> 4;       // output row group
    const int lr  = tid >> 2;      // x-load row 0..63
    const int lc4 = tid & 3;       // x-load float4 within 16-wide chunk
    const int wr  = tid >> 4;      // w-load row 0..15
    const int wc4 = tid & 15;      // w-load float4 col

    float acc[4][4];
    #pragma unroll
    for (int u = 0; u < 4; ++u)
        #pragma unroll
        for (int v = 0; v < 4; ++v) acc[u][v] = 0.f;

    const float4* xg = (const float4*)x;
    const float4* Wg = (const float4*)W;

    for (int kc = 0; kc < Cc/16; ++kc) {
        float4 xv = xg[(size_t)(m0 + lr) * (Cc/4) + kc*4 + lc4];
        float4 wv = Wg[(size_t)(kc*16 + wr) * (Dc/4) + wc4];
        __syncthreads();   // previous iteration's smem reads done
        const int kk = lc4 * 4;
        xsT[(kk+0)*68 + lr] = xv.x;
        xsT[(kk+1)*68 + lr] = xv.y;
        xsT[(kk+2)*68 + lr] = xv.z;
        xsT[(kk+3)*68 + lr] = xv.w;
        ((float4*)ws)[wr*16 + wc4] = wv;
        __syncthreads();
        #pragma unroll
        for (int k = 0; k < 16; ++k) {
            float4 a = *(const float4*)&xsT[k*68 + ty*4];
            float4 b = *(const float4*)&ws [k*64 + tx*4];
            acc[0][0] += a.x*b.x; acc[0][1] += a.x*b.y; acc[0][2] += a.x*b.z; acc[0][3] += a.x*b.w;
            acc[1][0] += a.y*b.x; acc[1][1] += a.y*b.y; acc[1][2] += a.y*b.z; acc[1][3] += a.y*b.w;
            acc[2][0] += a.z*b.x; acc[2][1] += a.z*b.y; acc[2][2] += a.z*b.z; acc[2][3] += a.z*b.w;
            acc[3][0] += a.w*b.x; acc[3][1] += a.w*b.y; acc[3][2] += a.w*b.z; acc[3][3] += a.w*b.w;
        }
    }

    float4 b4 = ((const float4*)bias)[tx];
    #pragma unroll
    for (int u = 0; u < 4; ++u) {
        float4 o;
        o.x = acc[u][0] + b4.x;
        o.y = acc[u][1] + b4.y;
        o.z = acc[u][2] + b4.z;
        o.w = acc[u][3] + b4.w;
        ((float4*)O)[(size_t)(m0 + ty*4 + u) * (Dc/4) + tx] = o;
    }
}

// ---------------------------------------------------------------------------
// Kernel 2: causal flash attention. grid = (T/64, B), block = 256.
// 4 threads per q-row; thread dp owns d-chunks {16*i + 4*dp} (conflict-free).
// Online softmax, per-row state duplicated across the 4 lanes of a group
// (score s is identical after the 2-step shfl reduce).
// ---------------------------------------------------------------------------
__global__ __launch_bounds__(256) void attn_kernel(float* __restrict__ out)
{
    __shared__ float sK[64*64];
    __shared__ float sV[64*64];

    const int tid = threadIdx.x;
    const int b  = blockIdx.y;
    const int q0 = blockIdx.x * 64;
    const int r  = tid >> 2;      // q-row within tile
    const int dp = tid & 3;       // d-partition
    const int q  = q0 + r;        // q index within batch
    const size_t qbase = ((size_t)b * Tc + q) * Dc;
    const float scale = 0.125f;   // 1/sqrt(64)

    float4 qv[4];
    #pragma unroll
    for (int i = 0; i < 4; ++i) {
        float4 t = *(const float4*)&g_Q[qbase + i*16 + dp*4];
        qv[i].x = t.x * scale; qv[i].y = t.y * scale;
        qv[i].z = t.z * scale; qv[i].w = t.w * scale;
    }
    float4 acc[4];
    #pragma unroll
    for (int i = 0; i < 4; ++i) { acc[i].x = acc[i].y = acc[i].z = acc[i].w = 0.f; }
    float m = -1e30f, l = 0.f;

    const int ntiles = blockIdx.x + 1;   // causal: k tiles [0, q0+64)
    for (int kt = 0; kt < ntiles; ++kt) {
        const int k0 = kt * 64;
        __syncthreads();
        const float4* Kg = (const float4*)&g_K[((size_t)b * Tc + k0) * Dc];
        const float4* Vg = (const float4*)&g_V[((size_t)b * Tc + k0) * Dc];
        #pragma unroll
        for (int i = tid; i < 1024; i += 256) {
            ((float4*)sK)[i] = Kg[i];
            ((float4*)sV)[i] = Vg[i];
        }
        __syncthreads();

        for (int j = 0; j < 64; ++j) {
            const float* kr = &sK[j*64 + dp*4];
            float4 k0v = *(const float4*)&kr[ 0];
            float4 k1v = *(const float4*)&kr[16];
            float4 k2v = *(const float4*)&kr[32];
            float4 k3v = *(const float4*)&kr[48];
            float s = qv[0].x*k0v.x + qv[0].y*k0v.y + qv[0].z*k0v.z + qv[0].w*k0v.w;
            s += qv[1].x*k1v.x + qv[1].y*k1v.y + qv[1].z*k1v.z + qv[1].w*k1v.w;
            s += qv[2].x*k2v.x + qv[2].y*k2v.y + qv[2].z*k2v.z + qv[2].w*k2v.w;
            s += qv[3].x*k3v.x + qv[3].y*k3v.y + qv[3].z*k3v.z + qv[3].w*k3v.w;
            s += __shfl_xor_sync(0xffffffffu, s, 1);
            s += __shfl_xor_sync(0xffffffffu, s, 2);

            if (k0 + j <= q) {
                float p;
                if (s > m) {
                    float c = __expf(m - s);
                    m = s;
                    l *= c;
                    #pragma unroll
                    for (int i = 0; i < 4; ++i) {
                        acc[i].x *= c; acc[i].y *= c; acc[i].z *= c; acc[i].w *= c;
                    }
                    p = 1.f;
                } else {
                    p = __expf(s - m);
                }
                l += p;
                const float* vr = &sV[j*64 + dp*4];
                float4 v0 = *(const float4*)&vr[ 0];
                float4 v1 = *(const float4*)&vr[16];
                float4 v2 = *(const float4*)&vr[32];
                float4 v3 = *(const float4*)&vr[48];
                acc[0].x += p*v0.x; acc[0].y += p*v0.y; acc[0].z += p*v0.z; acc[0].w += p*v0.w;
                acc[1].x += p*v1.x; acc[1].y += p*v1.y; acc[1].z += p*v1.z; acc[1].w += p*v1.w;
                acc[2].x += p*v2.x; acc[2].y += p*v2.y; acc[2].z += p*v2.z; acc[2].w += p*v2.w;
                acc[3].x += p*v3.x; acc[3].y += p*v3.y; acc[3].z += p*v3.z; acc[3].w += p*v3.w;
            }
        }
    }

    const float inv = 1.f / l;
    #pragma unroll
    for (int i = 0; i < 4; ++i) {
        float4 o;
        o.x = acc[i].x * inv; o.y = acc[i].y * inv;
        o.z = acc[i].z * inv; o.w = acc[i].w * inv;
        *(float4*)&out[qbase + i*16 + dp*4] = o;
    }
}

// ---------------------------------------------------------------------------
extern "C" void kernel_launch(void* const* d_in, const int* in_sizes, int n_in,
                              void* d_out, int out_size)
{
    const float* x  = (const float*)d_in[0];
    const float* Wq = (const float*)d_in[1];
    const float* bq = (const float*)d_in[2];
    const float* Wk = (const float*)d_in[3];
    const float* bk = (const float*)d_in[4];
    const float* Wv = (const float*)d_in[5];
    const float* bv = (const float*)d_in[6];
    float* out = (float*)d_out;

    dim3 g1(BT/64, 3);
    qkv_kernel<<<g1, 256>>>(x, Wq, bq, Wk, bk, Wv, bv);

    dim3 g2(Tc/64, Bc);
    attn_kernel<<<g2, 256>>>(out);
}

// round 2
// speedup vs baseline: 2.7538x; 2.7538x over previous
#include <cuda_runtime.h>

#define Bc 4
#define Tc 2048
#define Cc 1024
#define Dc 64
#define BT (Bc*Tc)
#define NQT (Tc/64)        // 32 q-tiles per batch
#define CHUNK 8            // k-tiles per attention block
#define MAXC 4             // max chunks per q-tile (32/8)
#define PAD 68             // padded smem row stride (floats), float4-aligned

// Scratch (allocation-free rule => __device__ globals)
__device__ float g_Q[BT*Dc];
__device__ float g_K[BT*Dc];
__device__ float g_V[BT*Dc];
__device__ float g_Op[Bc*NQT*MAXC*64*Dc];   // unnormalized partial O
__device__ float g_m [Bc*NQT*MAXC*64];      // per-row running max
__device__ float g_l [Bc*NQT*MAXC*64];      // per-row running denom

// ---------------------------------------------------------------------------
// Kernel 1: QKV projection.  grid = (BT/64, 3), block = 256  (unchanged)
// ---------------------------------------------------------------------------
__global__ __launch_bounds__(256) void qkv_kernel(
    const float* __restrict__ x,
    const float* __restrict__ Wq, const float* __restrict__ bq,
    const float* __restrict__ Wk, const float* __restrict__ bk,
    const float* __restrict__ Wv, const float* __restrict__ bv)
{
    __shared__ float xsT[16*68];
    __shared__ float ws [16*64];

    const int tid = threadIdx.x;
    const int which = blockIdx.y;
    const float* W;  const float* bias;  float* O;
    if (which == 0)      { W = Wq; bias = bq; O = g_Q; }
    else if (which == 1) { W = Wk; bias = bk; O = g_K; }
    else                 { W = Wv; bias = bv; O = g_V; }

    const int m0 = blockIdx.x * 64;
    const int tx = tid & 15;
    const int ty = tid >> 4;
    const int lr  = tid >> 2;
    const int lc4 = tid & 3;
    const int wr  = tid >> 4;
    const int wc4 = tid & 15;

    float acc[4][4];
    #pragma unroll
    for (int u = 0; u < 4; ++u)
        #pragma unroll
        for (int v = 0; v < 4; ++v) acc[u][v] = 0.f;

    const float4* xg = (const float4*)x;
    const float4* Wg = (const float4*)W;

    for (int kc = 0; kc < Cc/16; ++kc) {
        float4 xv = xg[(size_t)(m0 + lr) * (Cc/4) + kc*4 + lc4];
        float4 wv = Wg[(size_t)(kc*16 + wr) * (Dc/4) + wc4];
        __syncthreads();
        const int kk = lc4 * 4;
        xsT[(kk+0)*68 + lr] = xv.x;
        xsT[(kk+1)*68 + lr] = xv.y;
        xsT[(kk+2)*68 + lr] = xv.z;
        xsT[(kk+3)*68 + lr] = xv.w;
        ((float4*)ws)[wr*16 + wc4] = wv;
        __syncthreads();
        #pragma unroll
        for (int k = 0; k < 16; ++k) {
            float4 a = *(const float4*)&xsT[k*68 + ty*4];
            float4 b = *(const float4*)&ws [k*64 + tx*4];
            acc[0][0] += a.x*b.x; acc[0][1] += a.x*b.y; acc[0][2] += a.x*b.z; acc[0][3] += a.x*b.w;
            acc[1][0] += a.y*b.x; acc[1][1] += a.y*b.y; acc[1][2] += a.y*b.z; acc[1][3] += a.y*b.w;
            acc[2][0] += a.z*b.x; acc[2][1] += a.z*b.y; acc[2][2] += a.z*b.z; acc[2][3] += a.z*b.w;
            acc[3][0] += a.w*b.x; acc[3][1] += a.w*b.y; acc[3][2] += a.w*b.z; acc[3][3] += a.w*b.w;
        }
    }

    float4 b4 = ((const float4*)bias)[tx];
    #pragma unroll
    for (int u = 0; u < 4; ++u) {
        float4 o;
        o.x = acc[u][0] + b4.x;
        o.y = acc[u][1] + b4.y;
        o.z = acc[u][2] + b4.z;
        o.w = acc[u][3] + b4.w;
        ((float4*)O)[(size_t)(m0 + ty*4 + u) * (Dc/4) + tx] = o;
    }
}

// ---------------------------------------------------------------------------
// Kernel 2: split-KV flash attention, register-tiled GEMMs.
// grid = (MAXC, NQT, B), block = 256. Chunk c handles k-tiles [8c, min(8c+8,i+1)).
// Thread (tx,ty) owns S[ty*4..+3][tx*4..+3] and O[ty*4..+3][tx*4..+3].
// ---------------------------------------------------------------------------
__global__ __launch_bounds__(256, 2) void attn_kernel()
{
    const int c = blockIdx.x;
    const int i = blockIdx.y;
    const int b = blockIdx.z;
    const int kt0 = c * CHUNK;
    if (kt0 > i) return;
    const int kt1 = min(kt0 + CHUNK, i + 1);

    extern __shared__ __align__(16) float smem[];
    float* QsT = smem;                // [64 d][PAD rows]  (Q transposed, pre-scaled)
    float* KsT = smem + 64*PAD;       // [64 d][PAD rows]  (K transposed)
    float* Vs  = smem + 2*64*PAD;     // [64 j][PAD d]
    float* sPT = smem + 3*64*PAD;     // [64 j][PAD rows]  (P transposed)

    const int tid = threadIdx.x;
    const int tx = tid & 15;
    const int ty = tid >> 4;
    const float scale = 0.125f;

    // Load Q tile transposed + scaled
    {
        const float4* Qg = (const float4*)&g_Q[((size_t)b*Tc + i*64) * Dc];
        #pragma unroll
        for (int j = 0; j < 4; ++j) {
            int f = tid + 256*j;
            int row = f >> 4, c4 = f & 15;
            float4 v = Qg[f];
            QsT[(c4*4+0)*PAD + row] = v.x * scale;
            QsT[(c4*4+1)*PAD + row] = v.y * scale;
            QsT[(c4*4+2)*PAD + row] = v.z * scale;
            QsT[(c4*4+3)*PAD + row] = v.w * scale;
        }
    }

    float4 acc[4];
    #pragma unroll
    for (int u = 0; u < 4; ++u) { acc[u].x = acc[u].y = acc[u].z = acc[u].w = 0.f; }
    float m[4], l[4];
    #pragma unroll
    for (int u = 0; u < 4; ++u) { m[u] = -1e30f; l[u] = 0.f; }

    // Prefetch first tile into registers
    float4 kf[4], vf[4];
    {
        const float4* Kg = (const float4*)&g_K[((size_t)b*Tc + kt0*64) * Dc];
        const float4* Vg = (const float4*)&g_V[((size_t)b*Tc + kt0*64) * Dc];
        #pragma unroll
        for (int j = 0; j < 4; ++j) { kf[j] = Kg[tid + 256*j]; vf[j] = Vg[tid + 256*j]; }
    }

    for (int kt = kt0; kt < kt1; ++kt) {
        __syncthreads();   // previous iteration done reading KsT/Vs/sPT
        // Stage K (transposed) and V tiles into smem
        #pragma unroll
        for (int j = 0; j < 4; ++j) {
            int f = tid + 256*j;
            int row = f >> 4, c4 = f & 15;
            KsT[(c4*4+0)*PAD + row] = kf[j].x;
            KsT[(c4*4+1)*PAD + row] = kf[j].y;
            KsT[(c4*4+2)*PAD + row] = kf[j].z;
            KsT[(c4*4+3)*PAD + row] = kf[j].w;
            *(float4*)&Vs[row*PAD + c4*4] = vf[j];
        }
        __syncthreads();
        // Prefetch next tile
        if (kt + 1 < kt1) {
            const float4* Kg = (const float4*)&g_K[((size_t)b*Tc + (kt+1)*64) * Dc];
            const float4* Vg = (const float4*)&g_V[((size_t)b*Tc + (kt+1)*64) * Dc];
            #pragma unroll
            for (int j = 0; j < 4; ++j) { kf[j] = Kg[tid + 256*j]; vf[j] = Vg[tid + 256*j]; }
        }

        // GEMM1: S = Qs @ Ks^T  (4x4 per thread)
        float s[4][4];
        #pragma unroll
        for (int u = 0; u < 4; ++u)
            #pragma unroll
            for (int v = 0; v < 4; ++v) s[u][v] = 0.f;
        #pragma unroll 8
        for (int k = 0; k < 64; ++k) {
            float4 a = *(const float4*)&QsT[k*PAD + ty*4];
            float4 bb= *(const float4*)&KsT[k*PAD + tx*4];
            s[0][0] += a.x*bb.x; s[0][1] += a.x*bb.y; s[0][2] += a.x*bb.z; s[0][3] += a.x*bb.w;
            s[1][0] += a.y*bb.x; s[1][1] += a.y*bb.y; s[1][2] += a.y*bb.z; s[1][3] += a.y*bb.w;
            s[2][0] += a.z*bb.x; s[2][1] += a.z*bb.y; s[2][2] += a.z*bb.z; s[2][3] += a.z*bb.w;
            s[3][0] += a.w*bb.x; s[3][1] += a.w*bb.y; s[3][2] += a.w*bb.z; s[3][3] += a.w*bb.w;
        }

        // Causal mask on the diagonal tile
        if (kt == i) {
            #pragma unroll
            for (int u = 0; u < 4; ++u)
                #pragma unroll
                for (int v = 0; v < 4; ++v)
                    if (tx*4 + v > ty*4 + u) s[u][v] = -1e30f;
        }

        // Online softmax update (row reduce across 16 tx lanes within warp half)
        #pragma unroll
        for (int u = 0; u < 4; ++u) {
            float rm = fmaxf(fmaxf(s[u][0], s[u][1]), fmaxf(s[u][2], s[u][3]));
            rm = fmaxf(rm, __shfl_xor_sync(0xffffffffu, rm, 1));
            rm = fmaxf(rm, __shfl_xor_sync(0xffffffffu, rm, 2));
            rm = fmaxf(rm, __shfl_xor_sync(0xffffffffu, rm, 4));
            rm = fmaxf(rm, __shfl_xor_sync(0xffffffffu, rm, 8));
            float mn = fmaxf(m[u], rm);
            float cc = __expf(m[u] - mn);
            m[u] = mn;
            s[u][0] = __expf(s[u][0] - mn);
            s[u][1] = __expf(s[u][1] - mn);
            s[u][2] = __expf(s[u][2] - mn);
            s[u][3] = __expf(s[u][3] - mn);
            float rs = s[u][0] + s[u][1] + s[u][2] + s[u][3];
            rs += __shfl_xor_sync(0xffffffffu, rs, 1);
            rs += __shfl_xor_sync(0xffffffffu, rs, 2);
            rs += __shfl_xor_sync(0xffffffffu, rs, 4);
            rs += __shfl_xor_sync(0xffffffffu, rs, 8);
            l[u] = l[u]*cc + rs;
            acc[u].x *= cc; acc[u].y *= cc; acc[u].z *= cc; acc[u].w *= cc;
        }

        // Write P transposed to smem: sPT[j][row]
        #pragma unroll
        for (int u = 0; u < 4; ++u)
            #pragma unroll
            for (int v = 0; v < 4; ++v)
                sPT[(tx*4+v)*PAD + ty*4+u] = s[u][v];
        __syncthreads();

        // GEMM2: O += P @ V   (rows ty, d-cols tx)
        #pragma unroll 8
        for (int j = 0; j < 64; ++j) {
            float4 a = *(const float4*)&sPT[j*PAD + ty*4];
            float4 bb= *(const float4*)&Vs [j*PAD + tx*4];
            acc[0].x += a.x*bb.x; acc[0].y += a.x*bb.y; acc[0].z += a.x*bb.z; acc[0].w += a.x*bb.w;
            acc[1].x += a.y*bb.x; acc[1].y += a.y*bb.y; acc[1].z += a.y*bb.z; acc[1].w += a.y*bb.w;
            acc[2].x += a.z*bb.x; acc[2].y += a.z*bb.y; acc[2].z += a.z*bb.z; acc[2].w += a.z*bb.w;
            acc[3].x += a.w*bb.x; acc[3].y += a.w*bb.y; acc[3].z += a.w*bb.z; acc[3].w += a.w*bb.w;
        }
    }

    // Store partials (unnormalized)
    {
        float4* Op = (float4*)&g_Op[(size_t)(((b*NQT + i)*MAXC + c)) * 64 * Dc];
        #pragma unroll
        for (int u = 0; u < 4; ++u)
            Op[(ty*4+u)*16 + tx] = acc[u];
        if (tx == 0) {
            size_t rbase = (size_t)(((b*NQT + i)*MAXC + c)) * 64 + ty*4;
            #pragma unroll
            for (int u = 0; u < 4; ++u) { g_m[rbase+u] = m[u]; g_l[rbase+u] = l[u]; }
        }
    }
}

// ---------------------------------------------------------------------------
// Kernel 3: combine split-KV partials. grid = (NQT, B), block = 256.
// ---------------------------------------------------------------------------
__global__ __launch_bounds__(256) void combine_kernel(float* __restrict__ out)
{
    const int i = blockIdx.x;
    const int b = blockIdx.y;
    const int nc = i / CHUNK + 1;
    const int tid = threadIdx.x;

    const size_t pbase = (size_t)((b*NQT + i)*MAXC) * 64 * Dc / 4;   // float4 units
    const size_t rbase = (size_t)((b*NQT + i)*MAXC) * 64;

    #pragma unroll
    for (int t = 0; t < 4; ++t) {
        int f = tid + 256*t;            // f in [0,1024): row = f>>4, col4 = f&15
        int row = f >> 4;
        float M = -1e30f;
        float mm[MAXC];
        for (int cc = 0; cc < nc; ++cc) {
            mm[cc] = g_m[rbase + cc*64 + row];
            M = fmaxf(M, mm[cc]);
        }
        float L = 0.f;
        float4 o; o.x = o.y = o.z = o.w = 0.f;
        for (int cc = 0; cc < nc; ++cc) {
            float w = __expf(mm[cc] - M);
            L += w * g_l[rbase + cc*64 + row];
            float4 p = ((const float4*)g_Op)[pbase + cc*1024 + f];
            o.x += w*p.x; o.y += w*p.y; o.z += w*p.z; o.w += w*p.w;
        }
        float inv = 1.f / L;
        o.x *= inv; o.y *= inv; o.z *= inv; o.w *= inv;
        ((float4*)out)[((size_t)b*Tc + i*64 + row) * (Dc/4) + (f & 15)] = o;
    }
}

// ---------------------------------------------------------------------------
extern "C" void kernel_launch(void* const* d_in, const int* in_sizes, int n_in,
                              void* d_out, int out_size)
{
    const float* x  = (const float*)d_in[0];
    const float* Wq = (const float*)d_in[1];
    const float* bq = (const float*)d_in[2];
    const float* Wk = (const float*)d_in[3];
    const float* bk = (const float*)d_in[4];
    const float* Wv = (const float*)d_in[5];
    const float* bv = (const float*)d_in[6];
    float* out = (float*)d_out;

    dim3 g1(BT/64, 3);
    qkv_kernel<<<g1, 256>>>(x, Wq, bq, Wk, bk, Wv, bv);

    const int smem_bytes = 4 * 64 * PAD * sizeof(float);   // 69,632 B
    cudaFuncSetAttribute(attn_kernel, cudaFuncAttributeMaxDynamicSharedMemorySize, smem_bytes);
    dim3 g2(MAXC, NQT, Bc);
    attn_kernel<<<g2, 256, smem_bytes>>>();

    dim3 g3(NQT, Bc);
    combine_kernel<<<g3, 256>>>(out);
}

// round 3
// speedup vs baseline: 3.9697x; 1.4415x over previous
#include <cuda_runtime.h>

#define Bc 4
#define Tc 2048
#define Cc 1024
#define Dc 64
#define BT (Bc*Tc)
#define NQT (Tc/64)        // 32 q-tiles per batch
#define CHUNK 8            // k-tiles per attention block
#define MAXC 4             // max chunks per q-tile (32/8)
#define PAD 68             // padded smem row stride (floats), float4-aligned

// Scratch (allocation-free rule => __device__ globals)
__device__ float g_Q[BT*Dc];
__device__ float g_K[BT*Dc];
__device__ float g_V[BT*Dc];
__device__ float g_Op[Bc*NQT*MAXC*64*Dc];   // unnormalized partial O
__device__ float g_m [Bc*NQT*MAXC*64];      // per-row running max
__device__ float g_l [Bc*NQT*MAXC*64];      // per-row running denom

__device__ __forceinline__ unsigned f2tf32(float v) {
    unsigned u;
    asm("cvt.rna.tf32.f32 %0, %1;" : "=r"(u) : "f"(v));
    return u;
}

__device__ __forceinline__ void mma_tf32(float c[4], unsigned a0, unsigned a1,
                                         unsigned a2, unsigned a3,
                                         unsigned b0, unsigned b1) {
    asm volatile(
        "mma.sync.aligned.m16n8k8.row.col.f32.tf32.tf32.f32 "
        "{%0,%1,%2,%3}, {%4,%5,%6,%7}, {%8,%9}, {%0,%1,%2,%3};"
        : "+f"(c[0]), "+f"(c[1]), "+f"(c[2]), "+f"(c[3])
        : "r"(a0), "r"(a1), "r"(a2), "r"(a3), "r"(b0), "r"(b1));
}

// ---------------------------------------------------------------------------
// Kernel 1: QKV projection, TF32 tensor cores.
// grid = (BT/128, 3), block = 256 (8 warps). Block tile 128x64, BK=32.
// Warp (w&3, w>>2) owns a 32x32 output tile = 2x4 m16n8k8 mma tiles.
// A smem: [m][k] stride 44 (fragment loads conflict-free: bank=(12g+tg)%32).
// B smem: [k][n] stride 72 (fragment loads conflict-free: bank=(8tg+g)%32).
// ---------------------------------------------------------------------------
#define SA 44
#define SB 72

__global__ __launch_bounds__(256) void qkv_kernel(
    const float* __restrict__ x,
    const float* __restrict__ Wq, const float* __restrict__ bq,
    const float* __restrict__ Wk, const float* __restrict__ bk,
    const float* __restrict__ Wv, const float* __restrict__ bv)
{
    __shared__ unsigned As[128*SA];
    __shared__ unsigned Bs[32*SB];

    const int tid = threadIdx.x;
    const int which = blockIdx.y;
    const float* W;  const float* bias;  float* O;
    if (which == 0)      { W = Wq; bias = bq; O = g_Q; }
    else if (which == 1) { W = Wk; bias = bk; O = g_K; }
    else                 { W = Wv; bias = bv; O = g_V; }

    const int m0 = blockIdx.x * 128;
    const int w  = tid >> 5;
    const int lane = tid & 31;
    const int g  = lane >> 2;          // fragment group 0..7
    const int tg = lane & 3;           // fragment thread-in-group 0..3
    const int wm = (w & 3) * 32;       // warp m offset in tile
    const int wn = (w >> 2) * 32;      // warp n offset in tile

    // load-mapping
    const int ar  = tid >> 3;          // A row 0..31 (plus +32*jj), within 128 via jj
    const int ac4 = tid & 7;           // A k float4 0..7
    const int br  = tid >> 4;          // B k row 0..15 (plus +16)
    const int bc4 = tid & 15;          // B n float4 0..15

    float acc[2][4][4];
    #pragma unroll
    for (int mt = 0; mt < 2; ++mt)
        #pragma unroll
        for (int nt = 0; nt < 4; ++nt)
            #pragma unroll
            for (int q = 0; q < 4; ++q) acc[mt][nt][q] = 0.f;

    const float4* xg = (const float4*)x;
    const float4* Wg = (const float4*)W;

    float4 av[4], bv2[2];
    #pragma unroll
    for (int jj = 0; jj < 4; ++jj)
        av[jj] = xg[(size_t)(m0 + ar + 32*jj) * (Cc/4) + ac4];
    #pragma unroll
    for (int jj = 0; jj < 2; ++jj)
        bv2[jj] = Wg[(size_t)(br + 16*jj) * (Dc/4) + bc4];

    for (int kc = 0; kc < Cc/32; ++kc) {
        __syncthreads();   // previous iteration done reading smem
        #pragma unroll
        for (int jj = 0; jj < 4; ++jj) {
            unsigned* p = &As[(ar + 32*jj)*SA + ac4*4];
            p[0] = f2tf32(av[jj].x); p[1] = f2tf32(av[jj].y);
            p[2] = f2tf32(av[jj].z); p[3] = f2tf32(av[jj].w);
        }
        #pragma unroll
        for (int jj = 0; jj < 2; ++jj) {
            unsigned* p = &Bs[(br + 16*jj)*SB + bc4*4];
            p[0] = f2tf32(bv2[jj].x); p[1] = f2tf32(bv2[jj].y);
            p[2] = f2tf32(bv2[jj].z); p[3] = f2tf32(bv2[jj].w);
        }
        __syncthreads();
        if (kc + 1 < Cc/32) {
            #pragma unroll
            for (int jj = 0; jj < 4; ++jj)
                av[jj] = xg[(size_t)(m0 + ar + 32*jj) * (Cc/4) + (kc+1)*8 + ac4];
            #pragma unroll
            for (int jj = 0; jj < 2; ++jj)
                bv2[jj] = Wg[(size_t)((kc+1)*32 + br + 16*jj) * (Dc/4) + bc4];
        }

        #pragma unroll
        for (int ks = 0; ks < 4; ++ks) {
            const int k0 = ks * 8;
            unsigned a[2][4], b[4][2];
            #pragma unroll
            for (int mt = 0; mt < 2; ++mt) {
                const unsigned* base = &As[(wm + mt*16 + g)*SA + k0 + tg];
                a[mt][0] = base[0];
                a[mt][1] = base[8*SA];
                a[mt][2] = base[4];
                a[mt][3] = base[8*SA + 4];
            }
            #pragma unroll
            for (int nt = 0; nt < 4; ++nt) {
                const unsigned* base = &Bs[(k0 + tg)*SB + wn + nt*8 + g];
                b[nt][0] = base[0];
                b[nt][1] = base[4*SB];
            }
            #pragma unroll
            for (int mt = 0; mt < 2; ++mt)
                #pragma unroll
                for (int nt = 0; nt < 4; ++nt)
                    mma_tf32(acc[mt][nt], a[mt][0], a[mt][1], a[mt][2], a[mt][3],
                             b[nt][0], b[nt][1]);
        }
    }

    // Writeback with bias. c0,c1 at (g, 2tg..2tg+1); c2,c3 at (g+8, ...).
    #pragma unroll
    for (int nt = 0; nt < 4; ++nt) {
        const int col = wn + nt*8 + 2*tg;
        float bx = bias[col], by = bias[col+1];
        #pragma unroll
        for (int mt = 0; mt < 2; ++mt) {
            int row = m0 + wm + mt*16 + g;
            float2 o0; o0.x = acc[mt][nt][0] + bx; o0.y = acc[mt][nt][1] + by;
            float2 o1; o1.x = acc[mt][nt][2] + bx; o1.y = acc[mt][nt][3] + by;
            *(float2*)&O[(size_t)row*Dc + col]      = o0;
            *(float2*)&O[(size_t)(row+8)*Dc + col]  = o1;
        }
    }
}

// ---------------------------------------------------------------------------
// Kernel 2: split-KV flash attention, register-tiled GEMMs. (unchanged)
// ---------------------------------------------------------------------------
__global__ __launch_bounds__(256, 2) void attn_kernel()
{
    const int c = blockIdx.x;
    const int i = blockIdx.y;
    const int b = blockIdx.z;
    const int kt0 = c * CHUNK;
    if (kt0 > i) return;
    const int kt1 = min(kt0 + CHUNK, i + 1);

    extern __shared__ __align__(16) float smem[];
    float* QsT = smem;
    float* KsT = smem + 64*PAD;
    float* Vs  = smem + 2*64*PAD;
    float* sPT = smem + 3*64*PAD;

    const int tid = threadIdx.x;
    const int tx = tid & 15;
    const int ty = tid >> 4;
    const float scale = 0.125f;

    {
        const float4* Qg = (const float4*)&g_Q[((size_t)b*Tc + i*64) * Dc];
        #pragma unroll
        for (int j = 0; j < 4; ++j) {
            int f = tid + 256*j;
            int row = f >> 4, c4 = f & 15;
            float4 v = Qg[f];
            QsT[(c4*4+0)*PAD + row] = v.x * scale;
            QsT[(c4*4+1)*PAD + row] = v.y * scale;
            QsT[(c4*4+2)*PAD + row] = v.z * scale;
            QsT[(c4*4+3)*PAD + row] = v.w * scale;
        }
    }

    float4 acc[4];
    #pragma unroll
    for (int u = 0; u < 4; ++u) { acc[u].x = acc[u].y = acc[u].z = acc[u].w = 0.f; }
    float m[4], l[4];
    #pragma unroll
    for (int u = 0; u < 4; ++u) { m[u] = -1e30f; l[u] = 0.f; }

    float4 kf[4], vf[4];
    {
        const float4* Kg = (const float4*)&g_K[((size_t)b*Tc + kt0*64) * Dc];
        const float4* Vg = (const float4*)&g_V[((size_t)b*Tc + kt0*64) * Dc];
        #pragma unroll
        for (int j = 0; j < 4; ++j) { kf[j] = Kg[tid + 256*j]; vf[j] = Vg[tid + 256*j]; }
    }

    for (int kt = kt0; kt < kt1; ++kt) {
        __syncthreads();
        #pragma unroll
        for (int j = 0; j < 4; ++j) {
            int f = tid + 256*j;
            int row = f >> 4, c4 = f & 15;
            KsT[(c4*4+0)*PAD + row] = kf[j].x;
            KsT[(c4*4+1)*PAD + row] = kf[j].y;
            KsT[(c4*4+2)*PAD + row] = kf[j].z;
            KsT[(c4*4+3)*PAD + row] = kf[j].w;
            *(float4*)&Vs[row*PAD + c4*4] = vf[j];
        }
        __syncthreads();
        if (kt + 1 < kt1) {
            const float4* Kg = (const float4*)&g_K[((size_t)b*Tc + (kt+1)*64) * Dc];
            const float4* Vg = (const float4*)&g_V[((size_t)b*Tc + (kt+1)*64) * Dc];
            #pragma unroll
            for (int j = 0; j < 4; ++j) { kf[j] = Kg[tid + 256*j]; vf[j] = Vg[tid + 256*j]; }
        }

        float s[4][4];
        #pragma unroll
        for (int u = 0; u < 4; ++u)
            #pragma unroll
            for (int v = 0; v < 4; ++v) s[u][v] = 0.f;
        #pragma unroll 8
        for (int k = 0; k < 64; ++k) {
            float4 a = *(const float4*)&QsT[k*PAD + ty*4];
            float4 bb= *(const float4*)&KsT[k*PAD + tx*4];
            s[0][0] += a.x*bb.x; s[0][1] += a.x*bb.y; s[0][2] += a.x*bb.z; s[0][3] += a.x*bb.w;
            s[1][0] += a.y*bb.x; s[1][1] += a.y*bb.y; s[1][2] += a.y*bb.z; s[1][3] += a.y*bb.w;
            s[2][0] += a.z*bb.x; s[2][1] += a.z*bb.y; s[2][2] += a.z*bb.z; s[2][3] += a.z*bb.w;
            s[3][0] += a.w*bb.x; s[3][1] += a.w*bb.y; s[3][2] += a.w*bb.z; s[3][3] += a.w*bb.w;
        }

        if (kt == i) {
            #pragma unroll
            for (int u = 0; u < 4; ++u)
                #pragma unroll
                for (int v = 0; v < 4; ++v)
                    if (tx*4 + v > ty*4 + u) s[u][v] = -1e30f;
        }

        #pragma unroll
        for (int u = 0; u < 4; ++u) {
            float rm = fmaxf(fmaxf(s[u][0], s[u][1]), fmaxf(s[u][2], s[u][3]));
            rm = fmaxf(rm, __shfl_xor_sync(0xffffffffu, rm, 1));
            rm = fmaxf(rm, __shfl_xor_sync(0xffffffffu, rm, 2));
            rm = fmaxf(rm, __shfl_xor_sync(0xffffffffu, rm, 4));
            rm = fmaxf(rm, __shfl_xor_sync(0xffffffffu, rm, 8));
            float mn = fmaxf(m[u], rm);
            float cc = __expf(m[u] - mn);
            m[u] = mn;
            s[u][0] = __expf(s[u][0] - mn);
            s[u][1] = __expf(s[u][1] - mn);
            s[u][2] = __expf(s[u][2] - mn);
            s[u][3] = __expf(s[u][3] - mn);
            float rs = s[u][0] + s[u][1] + s[u][2] + s[u][3];
            rs += __shfl_xor_sync(0xffffffffu, rs, 1);
            rs += __shfl_xor_sync(0xffffffffu, rs, 2);
            rs += __shfl_xor_sync(0xffffffffu, rs, 4);
            rs += __shfl_xor_sync(0xffffffffu, rs, 8);
            l[u] = l[u]*cc + rs;
            acc[u].x *= cc; acc[u].y *= cc; acc[u].z *= cc; acc[u].w *= cc;
        }

        #pragma unroll
        for (int u = 0; u < 4; ++u)
            #pragma unroll
            for (int v = 0; v < 4; ++v)
                sPT[(tx*4+v)*PAD + ty*4+u] = s[u][v];
        __syncthreads();

        #pragma unroll 8
        for (int j = 0; j < 64; ++j) {
            float4 a = *(const float4*)&sPT[j*PAD + ty*4];
            float4 bb= *(const float4*)&Vs [j*PAD + tx*4];
            acc[0].x += a.x*bb.x; acc[0].y += a.x*bb.y; acc[0].z += a.x*bb.z; acc[0].w += a.x*bb.w;
            acc[1].x += a.y*bb.x; acc[1].y += a.y*bb.y; acc[1].z += a.y*bb.z; acc[1].w += a.y*bb.w;
            acc[2].x += a.z*bb.x; acc[2].y += a.z*bb.y; acc[2].z += a.z*bb.z; acc[2].w += a.z*bb.w;
            acc[3].x += a.w*bb.x; acc[3].y += a.w*bb.y; acc[3].z += a.w*bb.z; acc[3].w += a.w*bb.w;
        }
    }

    {
        float4* Op = (float4*)&g_Op[(size_t)(((b*NQT + i)*MAXC + c)) * 64 * Dc];
        #pragma unroll
        for (int u = 0; u < 4; ++u)
            Op[(ty*4+u)*16 + tx] = acc[u];
        if (tx == 0) {
            size_t rbase = (size_t)(((b*NQT + i)*MAXC + c)) * 64 + ty*4;
            #pragma unroll
            for (int u = 0; u < 4; ++u) { g_m[rbase+u] = m[u]; g_l[rbase+u] = l[u]; }
        }
    }
}

// ---------------------------------------------------------------------------
// Kernel 3: combine split-KV partials. grid = (NQT, B), block = 256.
// ---------------------------------------------------------------------------
__global__ __launch_bounds__(256) void combine_kernel(float* __restrict__ out)
{
    const int i = blockIdx.x;
    const int b = blockIdx.y;
    const int nc = i / CHUNK + 1;
    const int tid = threadIdx.x;

    const size_t pbase = (size_t)((b*NQT + i)*MAXC) * 64 * Dc / 4;
    const size_t rbase = (size_t)((b*NQT + i)*MAXC) * 64;

    #pragma unroll
    for (int t = 0; t < 4; ++t) {
        int f = tid + 256*t;
        int row = f >> 4;
        float M = -1e30f;
        float mm[MAXC];
        for (int cc = 0; cc < nc; ++cc) {
            mm[cc] = g_m[rbase + cc*64 + row];
            M = fmaxf(M, mm[cc]);
        }
        float L = 0.f;
        float4 o; o.x = o.y = o.z = o.w = 0.f;
        for (int cc = 0; cc < nc; ++cc) {
            float w = __expf(mm[cc] - M);
            L += w * g_l[rbase + cc*64 + row];
            float4 p = ((const float4*)g_Op)[pbase + cc*1024 + f];
            o.x += w*p.x; o.y += w*p.y; o.z += w*p.z; o.w += w*p.w;
        }
        float inv = 1.f / L;
        o.x *= inv; o.y *= inv; o.z *= inv; o.w *= inv;
        ((float4*)out)[((size_t)b*Tc + i*64 + row) * (Dc/4) + (f & 15)] = o;
    }
}

// ---------------------------------------------------------------------------
extern "C" void kernel_launch(void* const* d_in, const int* in_sizes, int n_in,
                              void* d_out, int out_size)
{
    const float* x  = (const float*)d_in[0];
    const float* Wq = (const float*)d_in[1];
    const float* bq = (const float*)d_in[2];
    const float* Wk = (const float*)d_in[3];
    const float* bk = (const float*)d_in[4];
    const float* Wv = (const float*)d_in[5];
    const float* bv = (const float*)d_in[6];
    float* out = (float*)d_out;

    dim3 g1(BT/128, 3);
    qkv_kernel<<<g1, 256>>>(x, Wq, bq, Wk, bk, Wv, bv);

    const int smem_bytes = 4 * 64 * PAD * sizeof(float);
    cudaFuncSetAttribute(attn_kernel, cudaFuncAttributeMaxDynamicSharedMemorySize, smem_bytes);
    dim3 g2(MAXC, NQT, Bc);
    attn_kernel<<<g2, 256, smem_bytes>>>();

    dim3 g3(NQT, Bc);
    combine_kernel<<<g3, 256>>>(out);
}

// round 4
// speedup vs baseline: 5.2963x; 1.3342x over previous
#include <cuda_runtime.h>

#define Bc 4
#define Tc 2048
#define Cc 1024
#define Dc 64
#define BT (Bc*Tc)

#define QT   128           // q rows per attention block
#define NQ2  (Tc/QT)       // 16 q-blocks per batch
#define SCH  4             // k-tiles (of 64 keys) per chunk
#define MAXC2 8            // max chunks per q-block
#define SKS  68            // K smem row stride (=4 mod 32)
#define SVS  72            // V smem row stride (=8 mod 32)

// Scratch (allocation-free rule => __device__ globals)
__device__ float g_Q[BT*Dc];
__device__ float g_K[BT*Dc];
__device__ float g_V[BT*Dc];
__device__ float g_Op2[(size_t)Bc*NQ2*MAXC2*QT*Dc];   // unnormalized partial O (16MB)
__device__ float g_m2[Bc*NQ2*MAXC2*QT];
__device__ float g_l2[Bc*NQ2*MAXC2*QT];

__device__ __forceinline__ unsigned f2tf32(float v) {
    unsigned u;
    asm("cvt.rna.tf32.f32 %0, %1;" : "=r"(u) : "f"(v));
    return u;
}

__device__ __forceinline__ void mma_tf32(float c[4], unsigned a0, unsigned a1,
                                         unsigned a2, unsigned a3,
                                         unsigned b0, unsigned b1) {
    asm volatile(
        "mma.sync.aligned.m16n8k8.row.col.f32.tf32.tf32.f32 "
        "{%0,%1,%2,%3}, {%4,%5,%6,%7}, {%8,%9}, {%0,%1,%2,%3};"
        : "+f"(c[0]), "+f"(c[1]), "+f"(c[2]), "+f"(c[3])
        : "r"(a0), "r"(a1), "r"(a2), "r"(a3), "r"(b0), "r"(b1));
}

// ---------------------------------------------------------------------------
// Kernel 1: QKV projection, TF32 tensor cores. grid=(BT/128, 3), block=256.
// Outputs are tf32-rounded (and Q pre-scaled by 1/sqrt(D)) for the attention
// kernel to consume without further conversion.
// ---------------------------------------------------------------------------
#define SA 44
#define SB 72

__global__ __launch_bounds__(256, 2) void qkv_kernel(
    const float* __restrict__ x,
    const float* __restrict__ Wq, const float* __restrict__ bq,
    const float* __restrict__ Wk, const float* __restrict__ bk,
    const float* __restrict__ Wv, const float* __restrict__ bv)
{
    __shared__ unsigned As[128*SA];
    __shared__ unsigned Bs[32*SB];

    const int tid = threadIdx.x;
    const int which = blockIdx.y;
    const float* W;  const float* bias;  float* O;
    if (which == 0)      { W = Wq; bias = bq; O = g_Q; }
    else if (which == 1) { W = Wk; bias = bk; O = g_K; }
    else                 { W = Wv; bias = bv; O = g_V; }
    const float osc = (which == 0) ? 0.125f : 1.0f;

    const int m0 = blockIdx.x * 128;
    const int w  = tid >> 5;
    const int lane = tid & 31;
    const int g  = lane >> 2;
    const int tg = lane & 3;
    const int wm = (w & 3) * 32;
    const int wn = (w >> 2) * 32;

    const int ar  = tid >> 3;
    const int ac4 = tid & 7;
    const int br  = tid >> 4;
    const int bc4 = tid & 15;

    float acc[2][4][4];
    #pragma unroll
    for (int mt = 0; mt < 2; ++mt)
        #pragma unroll
        for (int nt = 0; nt < 4; ++nt)
            #pragma unroll
            for (int q = 0; q < 4; ++q) acc[mt][nt][q] = 0.f;

    const float4* xg = (const float4*)x;
    const float4* Wg = (const float4*)W;

    float4 av[4], bv2[2];
    #pragma unroll
    for (int jj = 0; jj < 4; ++jj)
        av[jj] = xg[(size_t)(m0 + ar + 32*jj) * (Cc/4) + ac4];
    #pragma unroll
    for (int jj = 0; jj < 2; ++jj)
        bv2[jj] = Wg[(size_t)(br + 16*jj) * (Dc/4) + bc4];

    for (int kc = 0; kc < Cc/32; ++kc) {
        __syncthreads();
        #pragma unroll
        for (int jj = 0; jj < 4; ++jj) {
            unsigned* p = &As[(ar + 32*jj)*SA + ac4*4];
            p[0] = f2tf32(av[jj].x); p[1] = f2tf32(av[jj].y);
            p[2] = f2tf32(av[jj].z); p[3] = f2tf32(av[jj].w);
        }
        #pragma unroll
        for (int jj = 0; jj < 2; ++jj) {
            unsigned* p = &Bs[(br + 16*jj)*SB + bc4*4];
            p[0] = f2tf32(bv2[jj].x); p[1] = f2tf32(bv2[jj].y);
            p[2] = f2tf32(bv2[jj].z); p[3] = f2tf32(bv2[jj].w);
        }
        __syncthreads();
        if (kc + 1 < Cc/32) {
            #pragma unroll
            for (int jj = 0; jj < 4; ++jj)
                av[jj] = xg[(size_t)(m0 + ar + 32*jj) * (Cc/4) + (kc+1)*8 + ac4];
            #pragma unroll
            for (int jj = 0; jj < 2; ++jj)
                bv2[jj] = Wg[(size_t)((kc+1)*32 + br + 16*jj) * (Dc/4) + bc4];
        }

        #pragma unroll
        for (int ks = 0; ks < 4; ++ks) {
            const int k0 = ks * 8;
            unsigned a[2][4], b[4][2];
            #pragma unroll
            for (int mt = 0; mt < 2; ++mt) {
                const unsigned* base = &As[(wm + mt*16 + g)*SA + k0 + tg];
                a[mt][0] = base[0];
                a[mt][1] = base[8*SA];
                a[mt][2] = base[4];
                a[mt][3] = base[8*SA + 4];
            }
            #pragma unroll
            for (int nt = 0; nt < 4; ++nt) {
                const unsigned* base = &Bs[(k0 + tg)*SB + wn + nt*8 + g];
                b[nt][0] = base[0];
                b[nt][1] = base[4*SB];
            }
            #pragma unroll
            for (int mt = 0; mt < 2; ++mt)
                #pragma unroll
                for (int nt = 0; nt < 4; ++nt)
                    mma_tf32(acc[mt][nt], a[mt][0], a[mt][1], a[mt][2], a[mt][3],
                             b[nt][0], b[nt][1]);
        }
    }

    // Writeback: (acc+bias)*osc, tf32-rounded.
    #pragma unroll
    for (int nt = 0; nt < 4; ++nt) {
        const int col = wn + nt*8 + 2*tg;
        float bx = bias[col], by = bias[col+1];
        #pragma unroll
        for (int mt = 0; mt < 2; ++mt) {
            int row = m0 + wm + mt*16 + g;
            float2 o0, o1;
            o0.x = __uint_as_float(f2tf32((acc[mt][nt][0] + bx) * osc));
            o0.y = __uint_as_float(f2tf32((acc[mt][nt][1] + by) * osc));
            o1.x = __uint_as_float(f2tf32((acc[mt][nt][2] + bx) * osc));
            o1.y = __uint_as_float(f2tf32((acc[mt][nt][3] + by) * osc));
            *(float2*)&O[(size_t)row*Dc + col]      = o0;
            *(float2*)&O[(size_t)(row+8)*Dc + col]  = o1;
        }
    }
}

// ---------------------------------------------------------------------------
// Kernel 2: TF32 tensor-core flash attention, split-KV.
// grid = (MAXC2, NQ2, B), block = 256 (8 warps). Warp w owns q rows
// [i*128 + 16w, +16). Per k-tile: S via MMA, warp-local online softmax,
// P fragments built with butterfly shfls, PV via MMA.
// ---------------------------------------------------------------------------
__global__ __launch_bounds__(256) void attn_kernel()
{
    const int c = blockIdx.x;
    const int i = blockIdx.y;
    const int b = blockIdx.z;
    const int ktot = 2*(i+1);
    const int kt0 = c * SCH;
    if (kt0 >= ktot) return;
    const int kt1 = min(kt0 + SCH, ktot);

    extern __shared__ __align__(16) float smem[];
    float* Ks[2] = { smem,                smem + 64*SKS };
    float* Vs[2] = { smem + 2*64*SKS,     smem + 2*64*SKS + 64*SVS };

    const int tid = threadIdx.x;
    const int w = tid >> 5, lane = tid & 31;
    const int g = lane >> 2, tg = lane & 3;
    const int qrow = i*QT + w*16;            // warp's first global q row
    const size_t bT = (size_t)b * Tc;

    // Q A-fragments, persistent (g_Q pre-scaled + tf32-rounded)
    unsigned qa[8][4];
    {
        const float* Qp = &g_Q[(bT + qrow)*Dc];
        #pragma unroll
        for (int kc = 0; kc < 8; ++kc) {
            qa[kc][0] = __float_as_uint(Qp[(g  )*Dc + kc*8+tg  ]);
            qa[kc][1] = __float_as_uint(Qp[(g+8)*Dc + kc*8+tg  ]);
            qa[kc][2] = __float_as_uint(Qp[(g  )*Dc + kc*8+tg+4]);
            qa[kc][3] = __float_as_uint(Qp[(g+8)*Dc + kc*8+tg+4]);
        }
    }

    float o[8][4];
    #pragma unroll
    for (int nt = 0; nt < 8; ++nt)
        #pragma unroll
        for (int q = 0; q < 4; ++q) o[nt][q] = 0.f;
    float m0v = -1e30f, m1v = -1e30f, l0 = 0.f, l1 = 0.f;

    // Stage first tile
    #pragma unroll
    for (int j = 0; j < 4; ++j) {
        int f = tid + 256*j; int key = f >> 4, c4 = f & 15;
        *(float4*)&Ks[0][key*SKS + c4*4] =
            ((const float4*)&g_K[(bT + kt0*64)*Dc])[f];
        *(float4*)&Vs[0][key*SVS + c4*4] =
            ((const float4*)&g_V[(bT + kt0*64)*Dc])[f];
    }
    __syncthreads();

    for (int kt = kt0; kt < kt1; ++kt) {
        const int buf = (kt - kt0) & 1;
        const float* ks = Ks[buf];
        const float* vs = Vs[buf];

        // Prefetch next tile into registers
        float4 pk[4], pv[4];
        const bool more = (kt + 1 < kt1);
        if (more) {
            const float4* Kg = (const float4*)&g_K[(bT + (kt+1)*64)*Dc];
            const float4* Vg = (const float4*)&g_V[(bT + (kt+1)*64)*Dc];
            #pragma unroll
            for (int j = 0; j < 4; ++j) { pk[j] = Kg[tid+256*j]; pv[j] = Vg[tid+256*j]; }
        }

        const int kb = kt * 64;
        if (kb <= qrow + 15) {            // warp has visible keys in this tile
            // --- S = Q @ K^T ---
            float s[8][4];
            #pragma unroll
            for (int nt = 0; nt < 8; ++nt)
                { s[nt][0]=0.f; s[nt][1]=0.f; s[nt][2]=0.f; s[nt][3]=0.f; }
            #pragma unroll
            for (int nt = 0; nt < 8; ++nt) {
                const float* kp = &ks[(nt*8 + g)*SKS];
                #pragma unroll
                for (int kc = 0; kc < 8; ++kc) {
                    unsigned b0 = __float_as_uint(kp[kc*8 + tg]);
                    unsigned b1 = __float_as_uint(kp[kc*8 + tg + 4]);
                    mma_tf32(s[nt], qa[kc][0], qa[kc][1], qa[kc][2], qa[kc][3], b0, b1);
                }
            }

            // --- causal mask (only on diagonal tiles of this warp) ---
            if (kb + 63 > qrow) {
                const int r0 = qrow + g, r1 = r0 + 8;
                #pragma unroll
                for (int nt = 0; nt < 8; ++nt) {
                    int col = kb + nt*8 + 2*tg;
                    if (col   > r0) s[nt][0] = -1e30f;
                    if (col+1 > r0) s[nt][1] = -1e30f;
                    if (col   > r1) s[nt][2] = -1e30f;
                    if (col+1 > r1) s[nt][3] = -1e30f;
                }
            }

            // --- online softmax (warp-local; rows g and g+8) ---
            float rm0 = -1e30f, rm1 = -1e30f;
            #pragma unroll
            for (int nt = 0; nt < 8; ++nt) {
                rm0 = fmaxf(rm0, fmaxf(s[nt][0], s[nt][1]));
                rm1 = fmaxf(rm1, fmaxf(s[nt][2], s[nt][3]));
            }
            rm0 = fmaxf(rm0, __shfl_xor_sync(0xffffffffu, rm0, 1));
            rm0 = fmaxf(rm0, __shfl_xor_sync(0xffffffffu, rm0, 2));
            rm1 = fmaxf(rm1, __shfl_xor_sync(0xffffffffu, rm1, 1));
            rm1 = fmaxf(rm1, __shfl_xor_sync(0xffffffffu, rm1, 2));
            const float mn0 = fmaxf(m0v, rm0), mn1 = fmaxf(m1v, rm1);
            const float f0 = __expf(m0v - mn0), f1 = __expf(m1v - mn1);
            m0v = mn0; m1v = mn1;

            float rs0 = 0.f, rs1 = 0.f;
            #pragma unroll
            for (int nt = 0; nt < 8; ++nt) {
                s[nt][0] = __uint_as_float(f2tf32(__expf(s[nt][0] - mn0)));
                s[nt][1] = __uint_as_float(f2tf32(__expf(s[nt][1] - mn0)));
                s[nt][2] = __uint_as_float(f2tf32(__expf(s[nt][2] - mn1)));
                s[nt][3] = __uint_as_float(f2tf32(__expf(s[nt][3] - mn1)));
                rs0 += s[nt][0] + s[nt][1];
                rs1 += s[nt][2] + s[nt][3];
            }
            rs0 += __shfl_xor_sync(0xffffffffu, rs0, 1);
            rs0 += __shfl_xor_sync(0xffffffffu, rs0, 2);
            rs1 += __shfl_xor_sync(0xffffffffu, rs1, 1);
            rs1 += __shfl_xor_sync(0xffffffffu, rs1, 2);
            l0 = l0*f0 + rs0;
            l1 = l1*f1 + rs1;
            #pragma unroll
            for (int nt = 0; nt < 8; ++nt) {
                o[nt][0] *= f0; o[nt][1] *= f0;
                o[nt][2] *= f1; o[nt][3] *= f1;
            }

            // --- build P A-fragments in place (C-layout -> A-layout shfl) ---
            const int src0 = (lane & ~3) | (tg >> 1);
            const int src1 = src0 + 2;
            const bool odd = (tg & 1);
            #pragma unroll
            for (int kc = 0; kc < 8; ++kc) {
                float t00 = __shfl_sync(0xffffffffu, s[kc][0], src0);
                float t01 = __shfl_sync(0xffffffffu, s[kc][1], src0);
                float t20 = __shfl_sync(0xffffffffu, s[kc][2], src0);
                float t21 = __shfl_sync(0xffffffffu, s[kc][3], src0);
                float u00 = __shfl_sync(0xffffffffu, s[kc][0], src1);
                float u01 = __shfl_sync(0xffffffffu, s[kc][1], src1);
                float u20 = __shfl_sync(0xffffffffu, s[kc][2], src1);
                float u21 = __shfl_sync(0xffffffffu, s[kc][3], src1);
                s[kc][0] = odd ? t01 : t00;   // pa0: (row g,   key kc*8+tg)
                s[kc][1] = odd ? t21 : t20;   // pa1: (row g+8, key kc*8+tg)
                s[kc][2] = odd ? u01 : u00;   // pa2: (row g,   key kc*8+tg+4)
                s[kc][3] = odd ? u21 : u20;   // pa3: (row g+8, key kc*8+tg+4)
            }

            // --- O += P @ V ---
            #pragma unroll
            for (int nt = 0; nt < 8; ++nt) {
                #pragma unroll
                for (int kc = 0; kc < 8; ++kc) {
                    const float* vp = &vs[(kc*8 + tg)*SVS + nt*8 + g];
                    unsigned b0 = __float_as_uint(vp[0]);
                    unsigned b1 = __float_as_uint(vp[4*SVS]);
                    mma_tf32(o[nt],
                             __float_as_uint(s[kc][0]), __float_as_uint(s[kc][1]),
                             __float_as_uint(s[kc][2]), __float_as_uint(s[kc][3]),
                             b0, b1);
                }
            }
        }

        // Stage next tile into the other buffer
        if (more) {
            #pragma unroll
            for (int j = 0; j < 4; ++j) {
                int f = tid + 256*j; int key = f >> 4, c4 = f & 15;
                *(float4*)&Ks[buf^1][key*SKS + c4*4] = pk[j];
                *(float4*)&Vs[buf^1][key*SVS + c4*4] = pv[j];
            }
        }
        __syncthreads();
    }

    // Store partials (unnormalized) + per-row m, l
    const size_t pbase = ((size_t)(b*NQ2 + i)*MAXC2 + c) * (QT*Dc);
    #pragma unroll
    for (int nt = 0; nt < 8; ++nt) {
        const int colb = nt*8 + 2*tg;
        float2 o0; o0.x = o[nt][0]; o0.y = o[nt][1];
        float2 o1; o1.x = o[nt][2]; o1.y = o[nt][3];
        *(float2*)&g_Op2[pbase + (size_t)(w*16 + g    )*Dc + colb] = o0;
        *(float2*)&g_Op2[pbase + (size_t)(w*16 + g + 8)*Dc + colb] = o1;
    }
    if (tg == 0) {
        const size_t rb = ((size_t)(b*NQ2 + i)*MAXC2 + c) * QT + w*16;
        g_m2[rb + g]     = m0v;  g_l2[rb + g]     = l0;
        g_m2[rb + g + 8] = m1v;  g_l2[rb + g + 8] = l1;
    }
}

// ---------------------------------------------------------------------------
// Kernel 3: combine split-KV partials. grid = (NQ2, B), block = 256.
// ---------------------------------------------------------------------------
__global__ __launch_bounds__(256) void combine_kernel(float* __restrict__ out)
{
    const int i = blockIdx.x;
    const int b = blockIdx.y;
    const int nc = (2*(i+1) + SCH - 1) / SCH;
    const int tid = threadIdx.x;
    const size_t cb = (size_t)(b*NQ2 + i) * MAXC2;

    #pragma unroll
    for (int t = 0; t < 8; ++t) {
        int f = tid + 256*t;            // float4 index in [0, 2048)
        int row = f >> 4;
        float M = -1e30f;
        float mm[MAXC2];
        for (int cc = 0; cc < nc; ++cc) {
            mm[cc] = g_m2[(cb + cc)*QT + row];
            M = fmaxf(M, mm[cc]);
        }
        float L = 0.f;
        float4 o; o.x = o.y = o.z = o.w = 0.f;
        for (int cc = 0; cc < nc; ++cc) {
            float wgt = __expf(mm[cc] - M);
            L += wgt * g_l2[(cb + cc)*QT + row];
            float4 p = ((const float4*)g_Op2)[(cb + cc)*(QT*Dc/4) + f];
            o.x += wgt*p.x; o.y += wgt*p.y; o.z += wgt*p.z; o.w += wgt*p.w;
        }
        float inv = 1.f / L;
        o.x *= inv; o.y *= inv; o.z *= inv; o.w *= inv;
        ((float4*)out)[((size_t)b*Tc + i*QT + row)*(Dc/4) + (f & 15)] = o;
    }
}

// ---------------------------------------------------------------------------
extern "C" void kernel_launch(void* const* d_in, const int* in_sizes, int n_in,
                              void* d_out, int out_size)
{
    const float* x  = (const float*)d_in[0];
    const float* Wq = (const float*)d_in[1];
    const float* bq = (const float*)d_in[2];
    const float* Wk = (const float*)d_in[3];
    const float* bk = (const float*)d_in[4];
    const float* Wv = (const float*)d_in[5];
    const float* bv = (const float*)d_in[6];
    float* out = (float*)d_out;

    dim3 g1(BT/128, 3);
    qkv_kernel<<<g1, 256>>>(x, Wq, bq, Wk, bk, Wv, bv);

    const int smem_bytes = (2*64*SKS + 2*64*SVS) * (int)sizeof(float);  // 71,680
    cudaFuncSetAttribute(attn_kernel, cudaFuncAttributeMaxDynamicSharedMemorySize, smem_bytes);
    dim3 g2(MAXC2, NQ2, Bc);
    attn_kernel<<<g2, 256, smem_bytes>>>();

    dim3 g3(NQ2, Bc);
    combine_kernel<<<g3, 256>>>(out);
}

// round 5
// speedup vs baseline: 5.6494x; 1.0667x over previous
#include <cuda_runtime.h>

#define Bc 4
#define Tc 2048
#define Cc 1024
#define Dc 64
#define BT (Bc*Tc)

#define QT   128           // q rows per attention block
#define NQ2  (Tc/QT)       // 16 q-blocks per batch
#define SCH  4             // k-tiles (of 64 keys) per chunk
#define MAXC2 8            // max chunks per q-block
#define SKS  68            // K smem row stride (=4 mod 32), 272B (16B aligned)
#define SVS  72            // V smem row stride (=8 mod 32), 288B
#define SA   44            // qkv A smem row stride (=12 mod 32), 176B
#define SB   72            // qkv B smem row stride (=8 mod 32)

// Scratch (allocation-free rule => __device__ globals)
__device__ float g_Wr[3*Cc*Dc];                       // tf32-rounded weights
__device__ float g_Q[BT*Dc];
__device__ float g_K[BT*Dc];
__device__ float g_V[BT*Dc];
__device__ float g_Op2[(size_t)Bc*NQ2*MAXC2*QT*Dc];   // unnormalized partial O
__device__ float g_m2[Bc*NQ2*MAXC2*QT];
__device__ float g_l2[Bc*NQ2*MAXC2*QT];

__device__ __forceinline__ unsigned f2tf32(float v) {
    unsigned u;
    asm("cvt.rna.tf32.f32 %0, %1;" : "=r"(u) : "f"(v));
    return u;
}

__device__ __forceinline__ void mma_tf32(float c[4], unsigned a0, unsigned a1,
                                         unsigned a2, unsigned a3,
                                         unsigned b0, unsigned b1) {
    asm volatile(
        "mma.sync.aligned.m16n8k8.row.col.f32.tf32.tf32.f32 "
        "{%0,%1,%2,%3}, {%4,%5,%6,%7}, {%8,%9}, {%0,%1,%2,%3};"
        : "+f"(c[0]), "+f"(c[1]), "+f"(c[2]), "+f"(c[3])
        : "r"(a0), "r"(a1), "r"(a2), "r"(a3), "r"(b0), "r"(b1));
}

__device__ __forceinline__ void cp16(float* dst_smem, const float* src) {
    unsigned d = (unsigned)__cvta_generic_to_shared(dst_smem);
    asm volatile("cp.async.ca.shared.global [%0], [%1], 16;" :: "r"(d), "l"(src));
}
#define CP_COMMIT() asm volatile("cp.async.commit_group;")
#define CP_WAIT1()  asm volatile("cp.async.wait_group 1;")

// ---------------------------------------------------------------------------
// Kernel 0: pre-round W matrices to tf32 (once per call; x stays raw/truncated)
// grid = (Cc*Dc/4/256, 3) = (64, 3), block 256.
// ---------------------------------------------------------------------------
__global__ __launch_bounds__(256) void roundw_kernel(
    const float* __restrict__ Wq, const float* __restrict__ Wk,
    const float* __restrict__ Wv)
{
    const float* src = (blockIdx.y == 0) ? Wq : (blockIdx.y == 1) ? Wk : Wv;
    float* dst = g_Wr + (size_t)blockIdx.y * Cc * Dc;
    int idx = blockIdx.x * 256 + threadIdx.x;       // float4 index, 16384 per W
    float4 v = ((const float4*)src)[idx];
    uint4 r;
    r.x = f2tf32(v.x); r.y = f2tf32(v.y); r.z = f2tf32(v.z); r.w = f2tf32(v.w);
    ((uint4*)dst)[idx] = r;
}

// ---------------------------------------------------------------------------
// Kernel 1: QKV projection, TF32 MMA, cp.async 2-stage pipeline.
// grid = (BT/128, 3), block = 256 (8 warps), warp tile 32x32, BK=32.
// Outputs rna-rounded tf32 (Q pre-scaled by 1/8).
// ---------------------------------------------------------------------------
__global__ __launch_bounds__(256, 2) void qkv_kernel(
    const float* __restrict__ x,
    const float* __restrict__ bq, const float* __restrict__ bk,
    const float* __restrict__ bv)
{
    extern __shared__ __align__(16) float sm[];
    float* As = sm;                   // [2][128*SA]
    float* Bs = sm + 2*128*SA;        // [2][32*SB]

    const int tid = threadIdx.x;
    const int which = blockIdx.y;
    const float* W = g_Wr + (size_t)which * Cc * Dc;
    const float* bias;  float* O;
    if (which == 0)      { bias = bq; O = g_Q; }
    else if (which == 1) { bias = bk; O = g_K; }
    else                 { bias = bv; O = g_V; }
    const float osc = (which == 0) ? 0.125f : 1.0f;

    const int m0 = blockIdx.x * 128;
    const int w  = tid >> 5;
    const int lane = tid & 31;
    const int g  = lane >> 2;
    const int tg = lane & 3;
    const int wm = (w & 3) * 32;
    const int wn = (w >> 2) * 32;

    // cp.async mappings
    const int a_row = tid >> 3, a_c8 = tid & 7;     // A: 4 chunks/thread
    const int b_row = tid >> 4, b_c16 = tid & 15;   // B: 2 chunks/thread

    float acc[2][4][4];
    #pragma unroll
    for (int mt = 0; mt < 2; ++mt)
        #pragma unroll
        for (int nt = 0; nt < 4; ++nt)
            #pragma unroll
            for (int q = 0; q < 4; ++q) acc[mt][nt][q] = 0.f;

    // Prologue: stage kc=0 into buffer 0
    {
        #pragma unroll
        for (int j = 0; j < 4; ++j) {
            int row = a_row + 32*j;
            cp16(&As[row*SA + a_c8*4], &x[(size_t)(m0 + row)*Cc + a_c8*4]);
        }
        #pragma unroll
        for (int j = 0; j < 2; ++j) {
            int row = b_row + 16*j;
            cp16(&Bs[row*SB + b_c16*4], &W[(size_t)row*Dc + b_c16*4]);
        }
        CP_COMMIT();
    }

    const int NIT = Cc/32;
    for (int kc = 0; kc < NIT; ++kc) {
        const int buf = kc & 1;
        float* Ab = As + buf*128*SA;
        float* Bb = Bs + buf*32*SB;
        float* An = As + (buf^1)*128*SA;
        float* Bn = Bs + (buf^1)*32*SB;

        __syncthreads();   // everyone finished reading buf^1 (previous compute)
        if (kc + 1 < NIT) {
            #pragma unroll
            for (int j = 0; j < 4; ++j) {
                int row = a_row + 32*j;
                cp16(&An[row*SA + a_c8*4],
                     &x[(size_t)(m0 + row)*Cc + (kc+1)*32 + a_c8*4]);
            }
            #pragma unroll
            for (int j = 0; j < 2; ++j) {
                int row = b_row + 16*j;
                cp16(&Bn[row*SB + b_c16*4],
                     &W[(size_t)((kc+1)*32 + row)*Dc + b_c16*4]);
            }
        }
        CP_COMMIT();       // possibly-empty group keeps the wait count uniform
        CP_WAIT1();        // group kc complete
        __syncthreads();

        #pragma unroll
        for (int ks = 0; ks < 4; ++ks) {
            const int k0 = ks * 8;
            unsigned a[2][4], b[4][2];
            #pragma unroll
            for (int mt = 0; mt < 2; ++mt) {
                const float* base = &Ab[(wm + mt*16 + g)*SA + k0 + tg];
                a[mt][0] = __float_as_uint(base[0]);
                a[mt][1] = __float_as_uint(base[8*SA]);
                a[mt][2] = __float_as_uint(base[4]);
                a[mt][3] = __float_as_uint(base[8*SA + 4]);
            }
            #pragma unroll
            for (int nt = 0; nt < 4; ++nt) {
                const float* base = &Bb[(k0 + tg)*SB + wn + nt*8 + g];
                b[nt][0] = __float_as_uint(base[0]);
                b[nt][1] = __float_as_uint(base[4*SB]);
            }
            #pragma unroll
            for (int mt = 0; mt < 2; ++mt)
                #pragma unroll
                for (int nt = 0; nt < 4; ++nt)
                    mma_tf32(acc[mt][nt], a[mt][0], a[mt][1], a[mt][2], a[mt][3],
                             b[nt][0], b[nt][1]);
        }
    }

    // Writeback: (acc+bias)*osc, rna-rounded tf32.
    #pragma unroll
    for (int nt = 0; nt < 4; ++nt) {
        const int col = wn + nt*8 + 2*tg;
        float bx = bias[col], by = bias[col+1];
        #pragma unroll
        for (int mt = 0; mt < 2; ++mt) {
            int row = m0 + wm + mt*16 + g;
            float2 o0, o1;
            o0.x = __uint_as_float(f2tf32((acc[mt][nt][0] + bx) * osc));
            o0.y = __uint_as_float(f2tf32((acc[mt][nt][1] + by) * osc));
            o1.x = __uint_as_float(f2tf32((acc[mt][nt][2] + bx) * osc));
            o1.y = __uint_as_float(f2tf32((acc[mt][nt][3] + by) * osc));
            *(float2*)&O[(size_t)row*Dc + col]      = o0;
            *(float2*)&O[(size_t)(row+8)*Dc + col]  = o1;
        }
    }
}

// ---------------------------------------------------------------------------
// Kernel 2: TF32 tensor-core flash attention, split-KV, cp.async pipeline.
// grid = (MAXC2, NQ2, B), block = 256 (8 warps).
// ---------------------------------------------------------------------------
__global__ __launch_bounds__(256, 2) void attn_kernel()
{
    const int c = blockIdx.x;
    const int i = blockIdx.y;
    const int b = blockIdx.z;
    const int ktot = 2*(i+1);
    const int kt0 = c * SCH;
    if (kt0 >= ktot) return;
    const int kt1 = min(kt0 + SCH, ktot);

    extern __shared__ __align__(16) float smem[];
    float* Ksm = smem;                 // [2][64*SKS]
    float* Vsm = smem + 2*64*SKS;      // [2][64*SVS]

    const int tid = threadIdx.x;
    const int w = tid >> 5, lane = tid & 31;
    const int g = lane >> 2, tg = lane & 3;
    const int qrow = i*QT + w*16;
    const size_t bT = (size_t)b * Tc;

    // cp.async mapping: 4 chunks each for K and V per thread
    const int l_row = tid >> 2, l_c4 = tid & 3;   // row 0..63, 4 c-chunks of 4

    // Prologue: stage tile kt0 into buffer 0 (16B chunks; row has 16 chunks)
    {
        const float* Kg = &g_K[(bT + kt0*64)*Dc];
        const float* Vg = &g_V[(bT + kt0*64)*Dc];
        #pragma unroll
        for (int j = 0; j < 4; ++j)
            cp16(&Ksm[l_row*SKS + (l_c4*4 + j)*4], &Kg[(size_t)l_row*Dc + (l_c4*4 + j)*4]);
        #pragma unroll
        for (int j = 0; j < 4; ++j)
            cp16(&Vsm[l_row*SVS + (l_c4*4 + j)*4], &Vg[(size_t)l_row*Dc + (l_c4*4 + j)*4]);
        CP_COMMIT();
    }

    // Q A-fragments, persistent (g_Q pre-scaled + tf32-rounded)
    unsigned qa[8][4];
    {
        const float* Qp = &g_Q[(bT + qrow)*Dc];
        #pragma unroll
        for (int kc = 0; kc < 8; ++kc) {
            qa[kc][0] = __float_as_uint(Qp[(g  )*Dc + kc*8+tg  ]);
            qa[kc][1] = __float_as_uint(Qp[(g+8)*Dc + kc*8+tg  ]);
            qa[kc][2] = __float_as_uint(Qp[(g  )*Dc + kc*8+tg+4]);
            qa[kc][3] = __float_as_uint(Qp[(g+8)*Dc + kc*8+tg+4]);
        }
    }

    float o[8][4];
    #pragma unroll
    for (int nt = 0; nt < 8; ++nt)
        #pragma unroll
        for (int q = 0; q < 4; ++q) o[nt][q] = 0.f;
    float m0v = -1e30f, m1v = -1e30f, l0 = 0.f, l1 = 0.f;

    for (int kt = kt0; kt < kt1; ++kt) {
        const int buf = (kt - kt0) & 1;
        const float* ks = Ksm + buf*64*SKS;
        const float* vs = Vsm + buf*64*SVS;
        float* kn = Ksm + (buf^1)*64*SKS;
        float* vn = Vsm + (buf^1)*64*SVS;

        __syncthreads();   // previous compute done reading buf^1
        if (kt + 1 < kt1) {
            const float* Kg = &g_K[(bT + (kt+1)*64)*Dc];
            const float* Vg = &g_V[(bT + (kt+1)*64)*Dc];
            #pragma unroll
            for (int j = 0; j < 4; ++j)
                cp16(&kn[l_row*SKS + (l_c4*4 + j)*4], &Kg[(size_t)l_row*Dc + (l_c4*4 + j)*4]);
            #pragma unroll
            for (int j = 0; j < 4; ++j)
                cp16(&vn[l_row*SVS + (l_c4*4 + j)*4], &Vg[(size_t)l_row*Dc + (l_c4*4 + j)*4]);
        }
        CP_COMMIT();
        CP_WAIT1();        // tile kt resident
        __syncthreads();

        const int kb = kt * 64;
        if (kb <= qrow + 15) {            // warp has visible keys in this tile
            // --- S = Q @ K^T : kc outer, 8 independent accumulators ---
            float s[8][4];
            #pragma unroll
            for (int nt = 0; nt < 8; ++nt)
                { s[nt][0]=0.f; s[nt][1]=0.f; s[nt][2]=0.f; s[nt][3]=0.f; }
            #pragma unroll
            for (int kc = 0; kc < 8; ++kc) {
                #pragma unroll
                for (int nt = 0; nt < 8; ++nt) {
                    const float* kp = &ks[(nt*8 + g)*SKS + kc*8 + tg];
                    mma_tf32(s[nt], qa[kc][0], qa[kc][1], qa[kc][2], qa[kc][3],
                             __float_as_uint(kp[0]), __float_as_uint(kp[4]));
                }
            }

            // --- causal mask on diagonal tiles ---
            if (kb + 63 > qrow) {
                const int r0 = qrow + g, r1 = r0 + 8;
                #pragma unroll
                for (int nt = 0; nt < 8; ++nt) {
                    int col = kb + nt*8 + 2*tg;
                    if (col   > r0) s[nt][0] = -1e30f;
                    if (col+1 > r0) s[nt][1] = -1e30f;
                    if (col   > r1) s[nt][2] = -1e30f;
                    if (col+1 > r1) s[nt][3] = -1e30f;
                }
            }

            // --- online softmax (warp-local; rows g and g+8) ---
            float rm0 = -1e30f, rm1 = -1e30f;
            #pragma unroll
            for (int nt = 0; nt < 8; ++nt) {
                rm0 = fmaxf(rm0, fmaxf(s[nt][0], s[nt][1]));
                rm1 = fmaxf(rm1, fmaxf(s[nt][2], s[nt][3]));
            }
            rm0 = fmaxf(rm0, __shfl_xor_sync(0xffffffffu, rm0, 1));
            rm0 = fmaxf(rm0, __shfl_xor_sync(0xffffffffu, rm0, 2));
            rm1 = fmaxf(rm1, __shfl_xor_sync(0xffffffffu, rm1, 1));
            rm1 = fmaxf(rm1, __shfl_xor_sync(0xffffffffu, rm1, 2));
            const float mn0 = fmaxf(m0v, rm0), mn1 = fmaxf(m1v, rm1);
            const float f0 = __expf(m0v - mn0), f1 = __expf(m1v - mn1);
            m0v = mn0; m1v = mn1;

            float rs0 = 0.f, rs1 = 0.f;
            #pragma unroll
            for (int nt = 0; nt < 8; ++nt) {
                s[nt][0] = __uint_as_float(f2tf32(__expf(s[nt][0] - mn0)));
                s[nt][1] = __uint_as_float(f2tf32(__expf(s[nt][1] - mn0)));
                s[nt][2] = __uint_as_float(f2tf32(__expf(s[nt][2] - mn1)));
                s[nt][3] = __uint_as_float(f2tf32(__expf(s[nt][3] - mn1)));
                rs0 += s[nt][0] + s[nt][1];
                rs1 += s[nt][2] + s[nt][3];
            }
            rs0 += __shfl_xor_sync(0xffffffffu, rs0, 1);
            rs0 += __shfl_xor_sync(0xffffffffu, rs0, 2);
            rs1 += __shfl_xor_sync(0xffffffffu, rs1, 1);
            rs1 += __shfl_xor_sync(0xffffffffu, rs1, 2);
            l0 = l0*f0 + rs0;
            l1 = l1*f1 + rs1;
            #pragma unroll
            for (int nt = 0; nt < 8; ++nt) {
                o[nt][0] *= f0; o[nt][1] *= f0;
                o[nt][2] *= f1; o[nt][3] *= f1;
            }

            // --- build P A-fragments in place (C-layout -> A-layout shfl) ---
            const int src0 = (lane & ~3) | (tg >> 1);
            const int src1 = src0 + 2;
            const bool odd = (tg & 1);
            #pragma unroll
            for (int kc = 0; kc < 8; ++kc) {
                float t00 = __shfl_sync(0xffffffffu, s[kc][0], src0);
                float t01 = __shfl_sync(0xffffffffu, s[kc][1], src0);
                float t20 = __shfl_sync(0xffffffffu, s[kc][2], src0);
                float t21 = __shfl_sync(0xffffffffu, s[kc][3], src0);
                float u00 = __shfl_sync(0xffffffffu, s[kc][0], src1);
                float u01 = __shfl_sync(0xffffffffu, s[kc][1], src1);
                float u20 = __shfl_sync(0xffffffffu, s[kc][2], src1);
                float u21 = __shfl_sync(0xffffffffu, s[kc][3], src1);
                s[kc][0] = odd ? t01 : t00;
                s[kc][1] = odd ? t21 : t20;
                s[kc][2] = odd ? u01 : u00;
                s[kc][3] = odd ? u21 : u20;
            }

            // --- O += P @ V : kc outer, 8 independent chains ---
            #pragma unroll
            for (int kc = 0; kc < 8; ++kc) {
                #pragma unroll
                for (int nt = 0; nt < 8; ++nt) {
                    const float* vp = &vs[(kc*8 + tg)*SVS + nt*8 + g];
                    mma_tf32(o[nt],
                             __float_as_uint(s[kc][0]), __float_as_uint(s[kc][1]),
                             __float_as_uint(s[kc][2]), __float_as_uint(s[kc][3]),
                             __float_as_uint(vp[0]), __float_as_uint(vp[4*SVS]));
                }
            }
        }
    }

    // Store partials (unnormalized) + per-row m, l
    const size_t pbase = ((size_t)(b*NQ2 + i)*MAXC2 + c) * (QT*Dc);
    #pragma unroll
    for (int nt = 0; nt < 8; ++nt) {
        const int colb = nt*8 + 2*tg;
        float2 o0; o0.x = o[nt][0]; o0.y = o[nt][1];
        float2 o1; o1.x = o[nt][2]; o1.y = o[nt][3];
        *(float2*)&g_Op2[pbase + (size_t)(w*16 + g    )*Dc + colb] = o0;
        *(float2*)&g_Op2[pbase + (size_t)(w*16 + g + 8)*Dc + colb] = o1;
    }
    if (tg == 0) {
        const size_t rb = ((size_t)(b*NQ2 + i)*MAXC2 + c) * QT + w*16;
        g_m2[rb + g]     = m0v;  g_l2[rb + g]     = l0;
        g_m2[rb + g + 8] = m1v;  g_l2[rb + g + 8] = l1;
    }
}

// ---------------------------------------------------------------------------
// Kernel 3: combine split-KV partials. grid = (NQ2, B), block = 256.
// ---------------------------------------------------------------------------
__global__ __launch_bounds__(256) void combine_kernel(float* __restrict__ out)
{
    const int i = blockIdx.x;
    const int b = blockIdx.y;
    const int nc = (2*(i+1) + SCH - 1) / SCH;
    const int tid = threadIdx.x;
    const size_t cb = (size_t)(b*NQ2 + i) * MAXC2;

    #pragma unroll
    for (int t = 0; t < 8; ++t) {
        int f = tid + 256*t;            // float4 index in [0, 2048)
        int row = f >> 4;
        float M = -1e30f;
        float mm[MAXC2];
        for (int cc = 0; cc < nc; ++cc) {
            mm[cc] = g_m2[(cb + cc)*QT + row];
            M = fmaxf(M, mm[cc]);
        }
        float L = 0.f;
        float4 o; o.x = o.y = o.z = o.w = 0.f;
        for (int cc = 0; cc < nc; ++cc) {
            float wgt = __expf(mm[cc] - M);
            L += wgt * g_l2[(cb + cc)*QT + row];
            float4 p = ((const float4*)g_Op2)[(cb + cc)*(QT*Dc/4) + f];
            o.x += wgt*p.x; o.y += wgt*p.y; o.z += wgt*p.z; o.w += wgt*p.w;
        }
        float inv = 1.f / L;
        o.x *= inv; o.y *= inv; o.z *= inv; o.w *= inv;
        ((float4*)out)[((size_t)b*Tc + i*QT + row)*(Dc/4) + (f & 15)] = o;
    }
}

// ---------------------------------------------------------------------------
extern "C" void kernel_launch(void* const* d_in, const int* in_sizes, int n_in,
                              void* d_out, int out_size)
{
    const float* x  = (const float*)d_in[0];
    const float* Wq = (const float*)d_in[1];
    const float* bq = (const float*)d_in[2];
    const float* Wk = (const float*)d_in[3];
    const float* bk = (const float*)d_in[4];
    const float* Wv = (const float*)d_in[5];
    const float* bv = (const float*)d_in[6];
    float* out = (float*)d_out;

    dim3 g0(Cc*Dc/4/256, 3);            // (64, 3)
    roundw_kernel<<<g0, 256>>>(Wq, Wk, Wv);

    const int qkv_smem = (2*128*SA + 2*32*SB) * (int)sizeof(float);   // 63,488
    cudaFuncSetAttribute(qkv_kernel, cudaFuncAttributeMaxDynamicSharedMemorySize, qkv_smem);
    dim3 g1(BT/128, 3);
    qkv_kernel<<<g1, 256, qkv_smem>>>(x, bq, bk, bv);

    const int attn_smem = (2*64*SKS + 2*64*SVS) * (int)sizeof(float); // 71,680
    cudaFuncSetAttribute(attn_kernel, cudaFuncAttributeMaxDynamicSharedMemorySize, attn_smem);
    dim3 g2(MAXC2, NQ2, Bc);
    attn_kernel<<<g2, 256, attn_smem>>>();

    dim3 g3(NQ2, Bc);
    combine_kernel<<<g3, 256>>>(out);
}

// round 6
// speedup vs baseline: 7.4375x; 1.3165x over previous
#include <cuda_runtime.h>

#define Bc 4
#define Tc 2048
#define Cc 1024
#define Dc 64
#define BT (Bc*Tc)

#define QT   128           // q rows per attention block
#define NQ2  (Tc/QT)       // 16 q-blocks per batch
#define SCH  4             // k-tiles (of 64 keys) per chunk
#define MAXC2 8            // max chunks per q-block
#define SKS  68            // K smem row stride (=4 mod 32)
#define SVS  72            // V smem row stride (=8 mod 32)
#define SA   44            // qkv A smem row stride (=12 mod 32)
#define SB   72            // qkv B smem row stride (=8 mod 32)

// Scratch (allocation-free rule => __device__ globals)
__device__ float g_Wr[3*Cc*Dc];                       // tf32-rounded weights
__device__ float g_Q[BT*Dc];
__device__ float g_K[BT*Dc];
__device__ float g_V[BT*Dc];
__device__ float g_Op2[(size_t)Bc*NQ2*MAXC2*QT*Dc];   // unnormalized partial O
__device__ float g_m2[Bc*NQ2*MAXC2*QT];
__device__ float g_l2[Bc*NQ2*MAXC2*QT];

__device__ __forceinline__ unsigned f2tf32(float v) {
    unsigned u;
    asm("cvt.rna.tf32.f32 %0, %1;" : "=r"(u) : "f"(v));
    return u;
}

__device__ __forceinline__ void mma_tf32(float c[4], unsigned a0, unsigned a1,
                                         unsigned a2, unsigned a3,
                                         unsigned b0, unsigned b1) {
    asm volatile(
        "mma.sync.aligned.m16n8k8.row.col.f32.tf32.tf32.f32 "
        "{%0,%1,%2,%3}, {%4,%5,%6,%7}, {%8,%9}, {%0,%1,%2,%3};"
        : "+f"(c[0]), "+f"(c[1]), "+f"(c[2]), "+f"(c[3])
        : "r"(a0), "r"(a1), "r"(a2), "r"(a3), "r"(b0), "r"(b1));
}

__device__ __forceinline__ void cp16(float* dst_smem, const float* src) {
    unsigned d = (unsigned)__cvta_generic_to_shared(dst_smem);
    asm volatile("cp.async.ca.shared.global [%0], [%1], 16;" :: "r"(d), "l"(src));
}
#define CP_COMMIT() asm volatile("cp.async.commit_group;")
#define CP_WAIT1()  asm volatile("cp.async.wait_group 1;")

// ---------------------------------------------------------------------------
// Kernel 0: pre-round W matrices to tf32.
// ---------------------------------------------------------------------------
__global__ __launch_bounds__(256) void roundw_kernel(
    const float* __restrict__ Wq, const float* __restrict__ Wk,
    const float* __restrict__ Wv)
{
    const float* src = (blockIdx.y == 0) ? Wq : (blockIdx.y == 1) ? Wk : Wv;
    float* dst = g_Wr + (size_t)blockIdx.y * Cc * Dc;
    int idx = blockIdx.x * 256 + threadIdx.x;
    float4 v = ((const float4*)src)[idx];
    uint4 r;
    r.x = f2tf32(v.x); r.y = f2tf32(v.y); r.z = f2tf32(v.z); r.w = f2tf32(v.w);
    ((uint4*)dst)[idx] = r;
}

// ---------------------------------------------------------------------------
// Kernel 1: QKV projection, TF32 MMA, cp.async 2-stage pipeline.
// grid = (BT/64, 3) = (128,3), block = 128 (4 warps). Tile 64x64, BK=32.
// Warp (w&1, w>>1) owns 32x32. High occupancy: ~4-5 CTAs/SM resident.
// ---------------------------------------------------------------------------
__global__ __launch_bounds__(128) void qkv_kernel(
    const float* __restrict__ x,
    const float* __restrict__ bq, const float* __restrict__ bk,
    const float* __restrict__ bv)
{
    extern __shared__ __align__(16) float sm[];
    float* As = sm;                   // [2][64*SA]
    float* Bs = sm + 2*64*SA;         // [2][32*SB]

    const int tid = threadIdx.x;
    const int which = blockIdx.y;
    const float* W = g_Wr + (size_t)which * Cc * Dc;
    const float* bias;  float* O;
    if (which == 0)      { bias = bq; O = g_Q; }
    else if (which == 1) { bias = bk; O = g_K; }
    else                 { bias = bv; O = g_V; }
    const float osc = (which == 0) ? 0.125f : 1.0f;

    const int m0 = blockIdx.x * 64;
    const int w  = tid >> 5;
    const int lane = tid & 31;
    const int g  = lane >> 2;
    const int tg = lane & 3;
    const int wm = (w & 1) * 32;
    const int wn = (w >> 1) * 32;

    // cp.async mappings (128 threads)
    const int a_row = tid >> 3, a_c8 = tid & 7;     // A: 64x32, 4 chunks/thread
    const int b_row = tid >> 4, b_c16 = tid & 15;   // B: 32x64, 4 chunks/thread

    float acc[2][4][4];
    #pragma unroll
    for (int mt = 0; mt < 2; ++mt)
        #pragma unroll
        for (int nt = 0; nt < 4; ++nt)
            #pragma unroll
            for (int q = 0; q < 4; ++q) acc[mt][nt][q] = 0.f;

    // Prologue: stage kc=0 into buffer 0
    {
        #pragma unroll
        for (int j = 0; j < 4; ++j) {
            int row = a_row + 16*j;
            cp16(&As[row*SA + a_c8*4], &x[(size_t)(m0 + row)*Cc + a_c8*4]);
        }
        #pragma unroll
        for (int j = 0; j < 4; ++j) {
            int row = b_row + 8*j;
            cp16(&Bs[row*SB + b_c16*4], &W[(size_t)row*Dc + b_c16*4]);
        }
        CP_COMMIT();
    }

    const int NIT = Cc/32;
    for (int kc = 0; kc < NIT; ++kc) {
        const int buf = kc & 1;
        float* Ab = As + buf*64*SA;
        float* Bb = Bs + buf*32*SB;
        float* An = As + (buf^1)*64*SA;
        float* Bn = Bs + (buf^1)*32*SB;

        __syncthreads();
        if (kc + 1 < NIT) {
            #pragma unroll
            for (int j = 0; j < 4; ++j) {
                int row = a_row + 16*j;
                cp16(&An[row*SA + a_c8*4],
                     &x[(size_t)(m0 + row)*Cc + (kc+1)*32 + a_c8*4]);
            }
            #pragma unroll
            for (int j = 0; j < 4; ++j) {
                int row = b_row + 8*j;
                cp16(&Bn[row*SB + b_c16*4],
                     &W[(size_t)((kc+1)*32 + row)*Dc + b_c16*4]);
            }
        }
        CP_COMMIT();
        CP_WAIT1();
        __syncthreads();

        #pragma unroll
        for (int ks = 0; ks < 4; ++ks) {
            const int k0 = ks * 8;
            unsigned a[2][4], b[4][2];
            #pragma unroll
            for (int mt = 0; mt < 2; ++mt) {
                const float* base = &Ab[(wm + mt*16 + g)*SA + k0 + tg];
                a[mt][0] = __float_as_uint(base[0]);
                a[mt][1] = __float_as_uint(base[8*SA]);
                a[mt][2] = __float_as_uint(base[4]);
                a[mt][3] = __float_as_uint(base[8*SA + 4]);
            }
            #pragma unroll
            for (int nt = 0; nt < 4; ++nt) {
                const float* base = &Bb[(k0 + tg)*SB + wn + nt*8 + g];
                b[nt][0] = __float_as_uint(base[0]);
                b[nt][1] = __float_as_uint(base[4*SB]);
            }
            #pragma unroll
            for (int mt = 0; mt < 2; ++mt)
                #pragma unroll
                for (int nt = 0; nt < 4; ++nt)
                    mma_tf32(acc[mt][nt], a[mt][0], a[mt][1], a[mt][2], a[mt][3],
                             b[nt][0], b[nt][1]);
        }
    }

    // Writeback: (acc+bias)*osc, rna-rounded tf32.
    #pragma unroll
    for (int nt = 0; nt < 4; ++nt) {
        const int col = wn + nt*8 + 2*tg;
        float bx = bias[col], by = bias[col+1];
        #pragma unroll
        for (int mt = 0; mt < 2; ++mt) {
            int row = m0 + wm + mt*16 + g;
            float2 o0, o1;
            o0.x = __uint_as_float(f2tf32((acc[mt][nt][0] + bx) * osc));
            o0.y = __uint_as_float(f2tf32((acc[mt][nt][1] + by) * osc));
            o1.x = __uint_as_float(f2tf32((acc[mt][nt][2] + bx) * osc));
            o1.y = __uint_as_float(f2tf32((acc[mt][nt][3] + by) * osc));
            *(float2*)&O[(size_t)row*Dc + col]      = o0;
            *(float2*)&O[(size_t)(row+8)*Dc + col]  = o1;
        }
    }
}

// ---------------------------------------------------------------------------
// Kernel 2: TF32 tensor-core flash attention, split-KV, cp.async pipeline.
// grid = (MAXC2, NQ2, B), block = 256 (8 warps). (unchanged from R5)
// ---------------------------------------------------------------------------
__global__ __launch_bounds__(256, 2) void attn_kernel()
{
    const int c = blockIdx.x;
    const int i = blockIdx.y;
    const int b = blockIdx.z;
    const int ktot = 2*(i+1);
    const int kt0 = c * SCH;
    if (kt0 >= ktot) return;
    const int kt1 = min(kt0 + SCH, ktot);

    extern __shared__ __align__(16) float smem[];
    float* Ksm = smem;                 // [2][64*SKS]
    float* Vsm = smem + 2*64*SKS;      // [2][64*SVS]

    const int tid = threadIdx.x;
    const int w = tid >> 5, lane = tid & 31;
    const int g = lane >> 2, tg = lane & 3;
    const int qrow = i*QT + w*16;
    const size_t bT = (size_t)b * Tc;

    const int l_row = tid >> 2, l_c4 = tid & 3;

    {
        const float* Kg = &g_K[(bT + kt0*64)*Dc];
        const float* Vg = &g_V[(bT + kt0*64)*Dc];
        #pragma unroll
        for (int j = 0; j < 4; ++j)
            cp16(&Ksm[l_row*SKS + (l_c4*4 + j)*4], &Kg[(size_t)l_row*Dc + (l_c4*4 + j)*4]);
        #pragma unroll
        for (int j = 0; j < 4; ++j)
            cp16(&Vsm[l_row*SVS + (l_c4*4 + j)*4], &Vg[(size_t)l_row*Dc + (l_c4*4 + j)*4]);
        CP_COMMIT();
    }

    unsigned qa[8][4];
    {
        const float* Qp = &g_Q[(bT + qrow)*Dc];
        #pragma unroll
        for (int kc = 0; kc < 8; ++kc) {
            qa[kc][0] = __float_as_uint(Qp[(g  )*Dc + kc*8+tg  ]);
            qa[kc][1] = __float_as_uint(Qp[(g+8)*Dc + kc*8+tg  ]);
            qa[kc][2] = __float_as_uint(Qp[(g  )*Dc + kc*8+tg+4]);
            qa[kc][3] = __float_as_uint(Qp[(g+8)*Dc + kc*8+tg+4]);
        }
    }

    float o[8][4];
    #pragma unroll
    for (int nt = 0; nt < 8; ++nt)
        #pragma unroll
        for (int q = 0; q < 4; ++q) o[nt][q] = 0.f;
    float m0v = -1e30f, m1v = -1e30f, l0 = 0.f, l1 = 0.f;

    for (int kt = kt0; kt < kt1; ++kt) {
        const int buf = (kt - kt0) & 1;
        const float* ks = Ksm + buf*64*SKS;
        const float* vs = Vsm + buf*64*SVS;
        float* kn = Ksm + (buf^1)*64*SKS;
        float* vn = Vsm + (buf^1)*64*SVS;

        __syncthreads();
        if (kt + 1 < kt1) {
            const float* Kg = &g_K[(bT + (kt+1)*64)*Dc];
            const float* Vg = &g_V[(bT + (kt+1)*64)*Dc];
            #pragma unroll
            for (int j = 0; j < 4; ++j)
                cp16(&kn[l_row*SKS + (l_c4*4 + j)*4], &Kg[(size_t)l_row*Dc + (l_c4*4 + j)*4]);
            #pragma unroll
            for (int j = 0; j < 4; ++j)
                cp16(&vn[l_row*SVS + (l_c4*4 + j)*4], &Vg[(size_t)l_row*Dc + (l_c4*4 + j)*4]);
        }
        CP_COMMIT();
        CP_WAIT1();
        __syncthreads();

        const int kb = kt * 64;
        if (kb <= qrow + 15) {
            float s[8][4];
            #pragma unroll
            for (int nt = 0; nt < 8; ++nt)
                { s[nt][0]=0.f; s[nt][1]=0.f; s[nt][2]=0.f; s[nt][3]=0.f; }
            #pragma unroll
            for (int kc = 0; kc < 8; ++kc) {
                #pragma unroll
                for (int nt = 0; nt < 8; ++nt) {
                    const float* kp = &ks[(nt*8 + g)*SKS + kc*8 + tg];
                    mma_tf32(s[nt], qa[kc][0], qa[kc][1], qa[kc][2], qa[kc][3],
                             __float_as_uint(kp[0]), __float_as_uint(kp[4]));
                }
            }

            if (kb + 63 > qrow) {
                const int r0 = qrow + g, r1 = r0 + 8;
                #pragma unroll
                for (int nt = 0; nt < 8; ++nt) {
                    int col = kb + nt*8 + 2*tg;
                    if (col   > r0) s[nt][0] = -1e30f;
                    if (col+1 > r0) s[nt][1] = -1e30f;
                    if (col   > r1) s[nt][2] = -1e30f;
                    if (col+1 > r1) s[nt][3] = -1e30f;
                }
            }

            float rm0 = -1e30f, rm1 = -1e30f;
            #pragma unroll
            for (int nt = 0; nt < 8; ++nt) {
                rm0 = fmaxf(rm0, fmaxf(s[nt][0], s[nt][1]));
                rm1 = fmaxf(rm1, fmaxf(s[nt][2], s[nt][3]));
            }
            rm0 = fmaxf(rm0, __shfl_xor_sync(0xffffffffu, rm0, 1));
            rm0 = fmaxf(rm0, __shfl_xor_sync(0xffffffffu, rm0, 2));
            rm1 = fmaxf(rm1, __shfl_xor_sync(0xffffffffu, rm1, 1));
            rm1 = fmaxf(rm1, __shfl_xor_sync(0xffffffffu, rm1, 2));
            const float mn0 = fmaxf(m0v, rm0), mn1 = fmaxf(m1v, rm1);
            const float f0 = __expf(m0v - mn0), f1 = __expf(m1v - mn1);
            m0v = mn0; m1v = mn1;

            float rs0 = 0.f, rs1 = 0.f;
            #pragma unroll
            for (int nt = 0; nt < 8; ++nt) {
                s[nt][0] = __uint_as_float(f2tf32(__expf(s[nt][0] - mn0)));
                s[nt][1] = __uint_as_float(f2tf32(__expf(s[nt][1] - mn0)));
                s[nt][2] = __uint_as_float(f2tf32(__expf(s[nt][2] - mn1)));
                s[nt][3] = __uint_as_float(f2tf32(__expf(s[nt][3] - mn1)));
                rs0 += s[nt][0] + s[nt][1];
                rs1 += s[nt][2] + s[nt][3];
            }
            rs0 += __shfl_xor_sync(0xffffffffu, rs0, 1);
            rs0 += __shfl_xor_sync(0xffffffffu, rs0, 2);
            rs1 += __shfl_xor_sync(0xffffffffu, rs1, 1);
            rs1 += __shfl_xor_sync(0xffffffffu, rs1, 2);
            l0 = l0*f0 + rs0;
            l1 = l1*f1 + rs1;
            #pragma unroll
            for (int nt = 0; nt < 8; ++nt) {
                o[nt][0] *= f0; o[nt][1] *= f0;
                o[nt][2] *= f1; o[nt][3] *= f1;
            }

            const int src0 = (lane & ~3) | (tg >> 1);
            const int src1 = src0 + 2;
            const bool odd = (tg & 1);
            #pragma unroll
            for (int kc = 0; kc < 8; ++kc) {
                float t00 = __shfl_sync(0xffffffffu, s[kc][0], src0);
                float t01 = __shfl_sync(0xffffffffu, s[kc][1], src0);
                float t20 = __shfl_sync(0xffffffffu, s[kc][2], src0);
                float t21 = __shfl_sync(0xffffffffu, s[kc][3], src0);
                float u00 = __shfl_sync(0xffffffffu, s[kc][0], src1);
                float u01 = __shfl_sync(0xffffffffu, s[kc][1], src1);
                float u20 = __shfl_sync(0xffffffffu, s[kc][2], src1);
                float u21 = __shfl_sync(0xffffffffu, s[kc][3], src1);
                s[kc][0] = odd ? t01 : t00;
                s[kc][1] = odd ? t21 : t20;
                s[kc][2] = odd ? u01 : u00;
                s[kc][3] = odd ? u21 : u20;
            }

            #pragma unroll
            for (int kc = 0; kc < 8; ++kc) {
                #pragma unroll
                for (int nt = 0; nt < 8; ++nt) {
                    const float* vp = &vs[(kc*8 + tg)*SVS + nt*8 + g];
                    mma_tf32(o[nt],
                             __float_as_uint(s[kc][0]), __float_as_uint(s[kc][1]),
                             __float_as_uint(s[kc][2]), __float_as_uint(s[kc][3]),
                             __float_as_uint(vp[0]), __float_as_uint(vp[4*SVS]));
                }
            }
        }
    }

    const size_t pbase = ((size_t)(b*NQ2 + i)*MAXC2 + c) * (QT*Dc);
    #pragma unroll
    for (int nt = 0; nt < 8; ++nt) {
        const int colb = nt*8 + 2*tg;
        float2 o0; o0.x = o[nt][0]; o0.y = o[nt][1];
        float2 o1; o1.x = o[nt][2]; o1.y = o[nt][3];
        *(float2*)&g_Op2[pbase + (size_t)(w*16 + g    )*Dc + colb] = o0;
        *(float2*)&g_Op2[pbase + (size_t)(w*16 + g + 8)*Dc + colb] = o1;
    }
    if (tg == 0) {
        const size_t rb = ((size_t)(b*NQ2 + i)*MAXC2 + c) * QT + w*16;
        g_m2[rb + g]     = m0v;  g_l2[rb + g]     = l0;
        g_m2[rb + g + 8] = m1v;  g_l2[rb + g + 8] = l1;
    }
}

// ---------------------------------------------------------------------------
// Kernel 3: combine split-KV partials, parallelized.
// grid = (NQ2, B, 8), block = 256. One float4 per thread; nc loads unrolled.
// ---------------------------------------------------------------------------
__global__ __launch_bounds__(256) void combine_kernel(float* __restrict__ out)
{
    const int i = blockIdx.x;
    const int b = blockIdx.y;
    const int nc = (2*(i+1) + SCH - 1) / SCH;
    const size_t cb = (size_t)(b*NQ2 + i) * MAXC2;

    const int f = blockIdx.z * 256 + threadIdx.x;   // float4 index in [0, 2048)
    const int row = f >> 4;

    float M = -1e30f;
    float mm[MAXC2];
    #pragma unroll
    for (int cc = 0; cc < MAXC2; ++cc) {
        if (cc < nc) {
            mm[cc] = g_m2[(cb + cc)*QT + row];
            M = fmaxf(M, mm[cc]);
        }
    }
    float L = 0.f;
    float4 o; o.x = o.y = o.z = o.w = 0.f;
    #pragma unroll
    for (int cc = 0; cc < MAXC2; ++cc) {
        if (cc < nc) {
            float wgt = __expf(mm[cc] - M);
            L += wgt * g_l2[(cb + cc)*QT + row];
            float4 p = ((const float4*)g_Op2)[(cb + cc)*(QT*Dc/4) + f];
            o.x += wgt*p.x; o.y += wgt*p.y; o.z += wgt*p.z; o.w += wgt*p.w;
        }
    }
    float inv = 1.f / L;
    o.x *= inv; o.y *= inv; o.z *= inv; o.w *= inv;
    ((float4*)out)[((size_t)b*Tc + i*QT + row)*(Dc/4) + (f & 15)] = o;
}

// ---------------------------------------------------------------------------
extern "C" void kernel_launch(void* const* d_in, const int* in_sizes, int n_in,
                              void* d_out, int out_size)
{
    const float* x  = (const float*)d_in[0];
    const float* Wq = (const float*)d_in[1];
    const float* bq = (const float*)d_in[2];
    const float* Wk = (const float*)d_in[3];
    const float* bk = (const float*)d_in[4];
    const float* Wv = (const float*)d_in[5];
    const float* bv = (const float*)d_in[6];
    float* out = (float*)d_out;

    dim3 g0(Cc*Dc/4/256, 3);
    roundw_kernel<<<g0, 256>>>(Wq, Wk, Wv);

    const int qkv_smem = (2*64*SA + 2*32*SB) * (int)sizeof(float);    // 40,960
    cudaFuncSetAttribute(qkv_kernel, cudaFuncAttributeMaxDynamicSharedMemorySize, qkv_smem);
    dim3 g1(BT/64, 3);
    qkv_kernel<<<g1, 128, qkv_smem>>>(x, bq, bk, bv);

    const int attn_smem = (2*64*SKS + 2*64*SVS) * (int)sizeof(float); // 71,680
    cudaFuncSetAttribute(attn_kernel, cudaFuncAttributeMaxDynamicSharedMemorySize, attn_smem);
    dim3 g2(MAXC2, NQ2, Bc);
    attn_kernel<<<g2, 256, attn_smem>>>();

    dim3 g3(NQ2, Bc, 8);
    combine_kernel<<<g3, 256>>>(out);
}